// round 7
// baseline (speedup 1.0000x reference)
#include <cuda_runtime.h>
#include <cuda_fp16.h>

#define B_    64
#define P_    196
#define E_    2048
#define H_    512
#define EMB_  512
#define V_    10000
#define TCAP  50
#define TMAX  49
#define MP_   (B_*P_)            /* 12544 */

#define PRED_SZ  ((size_t)B_*TCAP*V_)   /* 32,000,000 */
#define ALPHA_SZ ((size_t)B_*TCAP*P_)   /* 627,200 */

// ---------------- scratch (device globals; no allocation allowed) ----------
__device__ __half g_xwx[(size_t)MP_*E_];    // ~51.5 MB (fp16)
__device__ __half g_feat16[(size_t)MP_*E_]; // ~51.5 MB (fp16 copy of features)
__device__ float g_fmean[B_*E_];
__device__ float g_h[B_*H_];
__device__ float g_hwh[B_*E_];
__device__ float g_lam[B_*P_];
__device__ float g_z[B_*E_];
__device__ float g_gate[B_*E_];
__device__ float g_gi[B_*3*H_];
__device__ float g_gh[B_*3*H_];

// ---------------- fast math ------------------------------------------------
__device__ __forceinline__ float ftanh(float x) {
    float y;
    asm("tanh.approx.f32 %0, %1;" : "=f"(y) : "f"(x));
    return y;
}
__device__ __forceinline__ float fsig(float x) {
    return 1.f / (1.f + __expf(-x));
}
__device__ __forceinline__ unsigned int f2tf32(float x) {
    unsigned int u;
    asm("cvt.rna.tf32.f32 %0, %1;" : "=r"(u) : "f"(x));
    return u;
}

// ---------------- zero output + write dec ----------------------------------
__global__ void k_zero(float* out, const int* lengths) {
    size_t n = PRED_SZ + ALPHA_SZ;
    size_t i = (size_t)blockIdx.x * blockDim.x + threadIdx.x;
    size_t stride = (size_t)gridDim.x * blockDim.x;
    for (size_t j = i; j < n; j += stride) out[j] = 0.f;
    if (i < B_) out[PRED_SZ + ALPHA_SZ + i] = (float)(lengths[i] - 1);
}

// ---------------- features -> fp16 copy ------------------------------------
__global__ void k_feat16(const float* __restrict__ feat) {
    size_t i = (size_t)blockIdx.x * 256 + threadIdx.x;   // over MP_*E_/4
    float4 v = ((const float4*)feat)[i];
    __half2 a = __floats2half2_rn(v.x, v.y);
    __half2 b = __floats2half2_rn(v.z, v.w);
    uint2 u;
    u.x = *(unsigned int*)&a;
    u.y = *(unsigned int*)&b;
    ((uint2*)g_feat16)[i] = u;
}

// ---------------- feature mean over P (float4) -----------------------------
__global__ void k_fmean(const float* __restrict__ feat) {
    int i = blockIdx.x * 256 + threadIdx.x;   // over B*E/4
    int b = i / (E_/4), e4 = i % (E_/4);
    const float4* fp = (const float4*)(feat + (size_t)b * P_ * E_) + e4;
    float4 s = make_float4(0.f, 0.f, 0.f, 0.f);
    #pragma unroll 4
    for (int p = 0; p < P_; p++) {
        float4 v = fp[(size_t)p * (E_/4)];
        s.x += v.x; s.y += v.y; s.z += v.z; s.w += v.w;
    }
    const float inv = 1.f / P_;
    s.x *= inv; s.y *= inv; s.z *= inv; s.w *= inv;
    ((float4*)g_fmean)[i] = s;
}

// ---------------- tf32 tensor-core GEMM: xwx(half) = A @ W^T + bias --------
// 128x128 block tile, BK=16, 256 threads = 8 warps (2 M x 4 N), warp tile
// 64x32 via m16n8k8 tf32 mma. Dims must be multiples of tile sizes.
__global__ void __launch_bounds__(256, 2)
k_gemm_tc(const float* __restrict__ A, const float* __restrict__ W,
          const float* __restrict__ bias, __half* __restrict__ C,
          int N, int K) {
    __shared__ float As[2][128][20];
    __shared__ float Ws[2][128][20];
    int tid = threadIdx.x;
    int m0 = blockIdx.y * 128, n0 = blockIdx.x * 128;
    int lr = tid >> 2;            // 0..63
    int lk = (tid & 3) * 4;       // 0,4,8,12
    int wid  = tid >> 5;          // 0..7
    int lane = tid & 31;
    int wm = wid & 1;             // 0..1  (M direction)
    int wn = wid >> 1;            // 0..3  (N direction)
    int g = lane >> 2, u = lane & 3;

    float acc[4][4][4] = {};      // [mt][nt][reg]

    // preload k-tile 0 into buffer 0 (tf32-rounded)
    #pragma unroll
    for (int r = 0; r < 2; r++) {
        int row = lr + r * 64;
        float4 v = *(const float4*)&A[(size_t)(m0 + row) * K + lk];
        As[0][row][lk+0] = __uint_as_float(f2tf32(v.x));
        As[0][row][lk+1] = __uint_as_float(f2tf32(v.y));
        As[0][row][lk+2] = __uint_as_float(f2tf32(v.z));
        As[0][row][lk+3] = __uint_as_float(f2tf32(v.w));
        float4 w = *(const float4*)&W[(size_t)(n0 + row) * K + lk];
        Ws[0][row][lk+0] = __uint_as_float(f2tf32(w.x));
        Ws[0][row][lk+1] = __uint_as_float(f2tf32(w.y));
        Ws[0][row][lk+2] = __uint_as_float(f2tf32(w.z));
        Ws[0][row][lk+3] = __uint_as_float(f2tf32(w.w));
    }
    __syncthreads();

    int buf = 0;
    for (int k0 = 0; k0 < K; k0 += 16) {
        bool more = (k0 + 16) < K;
        float4 pv[2], pw[2];
        if (more) {
            #pragma unroll
            for (int r = 0; r < 2; r++) {
                int row = lr + r * 64;
                pv[r] = *(const float4*)&A[(size_t)(m0 + row) * K + k0 + 16 + lk];
                pw[r] = *(const float4*)&W[(size_t)(n0 + row) * K + k0 + 16 + lk];
            }
        }
        #pragma unroll
        for (int ks = 0; ks < 16; ks += 8) {
            unsigned int af[4][4], bf[4][2];
            #pragma unroll
            for (int mt = 0; mt < 4; mt++) {
                int mb = wm * 64 + mt * 16;
                af[mt][0] = __float_as_uint(As[buf][mb + g    ][ks + u    ]);
                af[mt][1] = __float_as_uint(As[buf][mb + g + 8][ks + u    ]);
                af[mt][2] = __float_as_uint(As[buf][mb + g    ][ks + u + 4]);
                af[mt][3] = __float_as_uint(As[buf][mb + g + 8][ks + u + 4]);
            }
            #pragma unroll
            for (int nt = 0; nt < 4; nt++) {
                int nb = wn * 32 + nt * 8;
                bf[nt][0] = __float_as_uint(Ws[buf][nb + g][ks + u    ]);
                bf[nt][1] = __float_as_uint(Ws[buf][nb + g][ks + u + 4]);
            }
            #pragma unroll
            for (int mt = 0; mt < 4; mt++)
                #pragma unroll
                for (int nt = 0; nt < 4; nt++) {
                    asm volatile(
                        "mma.sync.aligned.m16n8k8.row.col.f32.tf32.tf32.f32 "
                        "{%0,%1,%2,%3}, {%4,%5,%6,%7}, {%8,%9}, {%0,%1,%2,%3};"
                        : "+f"(acc[mt][nt][0]), "+f"(acc[mt][nt][1]),
                          "+f"(acc[mt][nt][2]), "+f"(acc[mt][nt][3])
                        : "r"(af[mt][0]), "r"(af[mt][1]), "r"(af[mt][2]), "r"(af[mt][3]),
                          "r"(bf[nt][0]), "r"(bf[nt][1]));
                }
        }
        if (more) {
            int nb = buf ^ 1;
            #pragma unroll
            for (int r = 0; r < 2; r++) {
                int row = lr + r * 64;
                As[nb][row][lk+0] = __uint_as_float(f2tf32(pv[r].x));
                As[nb][row][lk+1] = __uint_as_float(f2tf32(pv[r].y));
                As[nb][row][lk+2] = __uint_as_float(f2tf32(pv[r].z));
                As[nb][row][lk+3] = __uint_as_float(f2tf32(pv[r].w));
                Ws[nb][row][lk+0] = __uint_as_float(f2tf32(pw[r].x));
                Ws[nb][row][lk+1] = __uint_as_float(f2tf32(pw[r].y));
                Ws[nb][row][lk+2] = __uint_as_float(f2tf32(pw[r].z));
                Ws[nb][row][lk+3] = __uint_as_float(f2tf32(pw[r].w));
            }
            __syncthreads();
            buf = nb;
        }
    }

    // epilogue: C fragments -> fp16 (c0,c1 are adjacent columns)
    #pragma unroll
    for (int mt = 0; mt < 4; mt++) {
        #pragma unroll
        for (int nt = 0; nt < 4; nt++) {
            int m = m0 + wm * 64 + mt * 16 + g;
            int n = n0 + wn * 32 + nt * 8 + u * 2;
            float b0 = bias[n], b1 = bias[n + 1];
            __half2 h0 = __floats2half2_rn(acc[mt][nt][0] + b0, acc[mt][nt][1] + b1);
            *(__half2*)&C[(size_t)m * N + n] = h0;
            __half2 h1 = __floats2half2_rn(acc[mt][nt][2] + b0, acc[mt][nt][3] + b1);
            *(__half2*)&C[(size_t)(m + 8) * N + n] = h1;
        }
    }
}

// ---------------- skinny GEMM: M fixed 64 ----------------------------------
template<int ACT>   // 0 = none, 1 = sigmoid
__global__ void k_gemm64(const float* __restrict__ A, const float* __restrict__ W,
                         const float* __restrict__ bias, float* __restrict__ C,
                         int N, int K, int ldc, const int* __restrict__ lengths, int t) {
    __shared__ float As[32][68];
    __shared__ float Ws[32][68];
    int tid = threadIdx.x;
    int n0 = blockIdx.x * 64;
    int lr = tid >> 3;            // 0..31
    int lk = (tid & 7) * 4;       // 0..28
    int ty = tid >> 4, tx = tid & 15;
    float acc[4][4] = {};
    for (int k0 = 0; k0 < K; k0 += 32) {
        #pragma unroll
        for (int r = 0; r < 2; r++) {
            int row = lr + r * 32;
            float4 v = *(const float4*)&A[(size_t)row * K + k0 + lk];
            As[lk+0][row] = v.x; As[lk+1][row] = v.y; As[lk+2][row] = v.z; As[lk+3][row] = v.w;
            int wn = n0 + row;
            float4 w = make_float4(0.f, 0.f, 0.f, 0.f);
            if (wn < N) w = *(const float4*)&W[(size_t)wn * K + k0 + lk];
            Ws[lk+0][row] = w.x; Ws[lk+1][row] = w.y; Ws[lk+2][row] = w.z; Ws[lk+3][row] = w.w;
        }
        __syncthreads();
        #pragma unroll
        for (int kk = 0; kk < 32; kk++) {
            float a[4], b[4];
            #pragma unroll
            for (int i = 0; i < 4; i++) a[i] = As[kk][ty*4 + i];
            #pragma unroll
            for (int j = 0; j < 4; j++) b[j] = Ws[kk][tx*4 + j];
            #pragma unroll
            for (int i = 0; i < 4; i++)
                #pragma unroll
                for (int j = 0; j < 4; j++)
                    acc[i][j] += a[i] * b[j];
        }
        __syncthreads();
    }
    #pragma unroll
    for (int i = 0; i < 4; i++) {
        int b = ty*4 + i;
        if (lengths && (lengths[b] - 1 < t)) continue;   // masked row: leave zeros
        #pragma unroll
        for (int j = 0; j < 4; j++) {
            int n = n0 + tx*4 + j;
            if (n < N) {
                float v = acc[i][j] + bias[n];
                if (ACT == 1) v = fsig(v);
                C[(size_t)b * ldc + n] = v;
            }
        }
    }
}

// ---------------- fused step GEMM 1: h_wh (blocks 0..31) + gate (32..63) ---
__global__ void k_step1(const float* __restrict__ Wh_w, const float* __restrict__ Wh_b,
                        const float* __restrict__ fb_w, const float* __restrict__ fb_b) {
    bool sig = blockIdx.x >= (E_/64);
    int n0 = (sig ? blockIdx.x - E_/64 : blockIdx.x) * 64;
    const float* W    = sig ? fb_w : Wh_w;
    const float* bias = sig ? fb_b : Wh_b;
    float* C          = sig ? g_gate : g_hwh;
    __shared__ float As[32][68];
    __shared__ float Ws[32][68];
    int tid = threadIdx.x;
    int lr = tid >> 3;
    int lk = (tid & 7) * 4;
    int ty = tid >> 4, tx = tid & 15;
    float acc[4][4] = {};
    for (int k0 = 0; k0 < H_; k0 += 32) {
        #pragma unroll
        for (int r = 0; r < 2; r++) {
            int row = lr + r * 32;
            float4 v = *(const float4*)&g_h[(size_t)row * H_ + k0 + lk];
            As[lk+0][row] = v.x; As[lk+1][row] = v.y; As[lk+2][row] = v.z; As[lk+3][row] = v.w;
            float4 w = *(const float4*)&W[(size_t)(n0 + row) * H_ + k0 + lk];
            Ws[lk+0][row] = w.x; Ws[lk+1][row] = w.y; Ws[lk+2][row] = w.z; Ws[lk+3][row] = w.w;
        }
        __syncthreads();
        #pragma unroll
        for (int kk = 0; kk < 32; kk++) {
            float a[4], b[4];
            #pragma unroll
            for (int i = 0; i < 4; i++) a[i] = As[kk][ty*4 + i];
            #pragma unroll
            for (int j = 0; j < 4; j++) b[j] = Ws[kk][tx*4 + j];
            #pragma unroll
            for (int i = 0; i < 4; i++)
                #pragma unroll
                for (int j = 0; j < 4; j++)
                    acc[i][j] += a[i] * b[j];
        }
        __syncthreads();
    }
    #pragma unroll
    for (int i = 0; i < 4; i++) {
        int b = ty*4 + i;
        #pragma unroll
        for (int j = 0; j < 4; j++) {
            int n = n0 + tx*4 + j;
            float v = acc[i][j] + bias[n];
            if (sig) v = fsig(v);
            C[(size_t)b * E_ + n] = v;
        }
    }
}

// ---------------- fused step GEMM 2: gi (blocks 0..23) + gh (24..47) -------
__global__ void k_gates(const float* __restrict__ w_ih, const float* __restrict__ b_ih,
                        const float* __restrict__ w_hh, const float* __restrict__ b_hh,
                        const float* __restrict__ embed, const int* __restrict__ captions,
                        int t) {
    const int NB = (3*H_)/64;           // 24
    bool is_gi = blockIdx.x < NB;
    int n0 = (is_gi ? blockIdx.x : blockIdx.x - NB) * 64;
    const float* W    = is_gi ? w_ih : w_hh;
    const float* bias = is_gi ? b_ih : b_hh;
    float* C          = is_gi ? g_gi : g_gh;
    int K             = is_gi ? (E_ + EMB_) : H_;
    __shared__ float As[32][68];
    __shared__ float Ws[32][68];
    int tid = threadIdx.x;
    int lr = tid >> 3;
    int lk = (tid & 7) * 4;
    int ty = tid >> 4, tx = tid & 15;
    float acc[4][4] = {};
    for (int k0 = 0; k0 < K; k0 += 32) {
        #pragma unroll
        for (int r = 0; r < 2; r++) {
            int row = lr + r * 32;
            int k = k0 + lk;
            float4 v;
            if (is_gi) {
                if (k < E_) {
                    float4 g = *(const float4*)&g_gate[(size_t)row * E_ + k];
                    float4 z = *(const float4*)&g_z[(size_t)row * E_ + k];
                    v = make_float4(g.x*z.x, g.y*z.y, g.z*z.z, g.w*z.w);
                } else {
                    int cap = captions[row * TCAP + t];
                    v = *(const float4*)&embed[(size_t)cap * EMB_ + (k - E_)];
                }
            } else {
                v = *(const float4*)&g_h[(size_t)row * H_ + k];
            }
            As[lk+0][row] = v.x; As[lk+1][row] = v.y; As[lk+2][row] = v.z; As[lk+3][row] = v.w;
            float4 w = *(const float4*)&W[(size_t)(n0 + row) * K + k];
            Ws[lk+0][row] = w.x; Ws[lk+1][row] = w.y; Ws[lk+2][row] = w.z; Ws[lk+3][row] = w.w;
        }
        __syncthreads();
        #pragma unroll
        for (int kk = 0; kk < 32; kk++) {
            float a[4], b[4];
            #pragma unroll
            for (int i = 0; i < 4; i++) a[i] = As[kk][ty*4 + i];
            #pragma unroll
            for (int j = 0; j < 4; j++) b[j] = Ws[kk][tx*4 + j];
            #pragma unroll
            for (int i = 0; i < 4; i++)
                #pragma unroll
                for (int j = 0; j < 4; j++)
                    acc[i][j] += a[i] * b[j];
        }
        __syncthreads();
    }
    #pragma unroll
    for (int i = 0; i < 4; i++) {
        int b = ty*4 + i;
        #pragma unroll
        for (int j = 0; j < 4; j++) {
            int n = n0 + tx*4 + j;
            C[(size_t)b * (3*H_) + n] = acc[i][j] + bias[n];
        }
    }
}

// ---------------- attention: lam[b,p] = V . tanh(xwx16[b,p]+h_wh[b]) + Vb --
__global__ void k_lam(const float* __restrict__ Vw, const float* __restrict__ Vb) {
    int bp = blockIdx.x;            // 0..12543
    int b  = bp / P_;
    int tid = threadIdx.x;
    const uint2*  xw2 = (const uint2*)(g_xwx + (size_t)bp * E_);   // 2 half2 per uint2
    const float4* hw4 = (const float4*)(g_hwh + (size_t)b * E_);
    const float4* vw4 = (const float4*)Vw;
    float s = 0.f;
    #pragma unroll
    for (int q = 0; q < 2; q++) {
        int i = tid * 2 + q;                 // float4-granule index, 0..511
        uint2 u = xw2[i];
        __half2 xa = *(__half2*)&u.x;
        __half2 xb = *(__half2*)&u.y;
        float2 fa = __half22float2(xa);
        float2 fb = __half22float2(xb);
        float4 h = hw4[i];
        float4 v = vw4[i];
        s += ftanh(fa.x + h.x) * v.x + ftanh(fa.y + h.y) * v.y
           + ftanh(fb.x + h.z) * v.z + ftanh(fb.y + h.w) * v.w;
    }
    __shared__ float red[8];
    int lane = tid & 31, w = tid >> 5;
    #pragma unroll
    for (int o = 16; o > 0; o >>= 1) s += __shfl_xor_sync(0xffffffffu, s, o);
    if (lane == 0) red[w] = s;
    __syncthreads();
    if (tid == 0) {
        float tot = 0.f;
        #pragma unroll
        for (int i = 0; i < 8; i++) tot += red[i];
        g_lam[bp] = tot + Vb[0];
    }
}

// ---------------- fused softmax + z ----------------------------------------
// 2 blocks per batch row (e-halves); both recompute the cheap softmax from
// g_lam; even block also writes masked alphas to the output.
__global__ void k_z(float* __restrict__ out_alphas, const int* __restrict__ lengths, int t) {
    int b  = blockIdx.x >> 1;
    int tid = threadIdx.x;
    int lane = tid & 31, w = tid >> 5;
    __shared__ float red[8];
    __shared__ float bmax, bsum;
    __shared__ float al[P_];

    float v = (tid < P_) ? g_lam[b * P_ + tid] : -3.4e38f;
    float m = v;
    #pragma unroll
    for (int o = 16; o > 0; o >>= 1) m = fmaxf(m, __shfl_xor_sync(0xffffffffu, m, o));
    if (lane == 0) red[w] = m;
    __syncthreads();
    if (tid == 0) {
        float mm = red[0];
        #pragma unroll
        for (int i = 1; i < 8; i++) mm = fmaxf(mm, red[i]);
        bmax = mm;
    }
    __syncthreads();
    float ex = (tid < P_) ? __expf(v - bmax) : 0.f;
    float s = ex;
    #pragma unroll
    for (int o = 16; o > 0; o >>= 1) s += __shfl_xor_sync(0xffffffffu, s, o);
    if (lane == 0) red[w] = s;
    __syncthreads();
    if (tid == 0) {
        float ss = 0.f;
        #pragma unroll
        for (int i = 0; i < 8; i++) ss += red[i];
        bsum = ss;
    }
    __syncthreads();
    if (tid < P_) {
        float a = ex / bsum;
        al[tid] = a;
        if (((blockIdx.x & 1) == 0) && (lengths[b] - 1 >= t))
            out_alphas[(size_t)b * TCAP * P_ + (size_t)t * P_ + tid] = a;
    }
    __syncthreads();

    int e4 = ((blockIdx.x & 1) << 8) + tid;     // float4-granule, 0..511
    const uint2* fp = (const uint2*)(g_feat16 + (size_t)b * P_ * E_) + e4;
    float4 acc = make_float4(0.f, 0.f, 0.f, 0.f);
    #pragma unroll 4
    for (int p = 0; p < P_; p++) {
        float a = al[p];
        uint2 u = fp[(size_t)p * (E_/4)];
        float2 fa = __half22float2(*(__half2*)&u.x);
        float2 fb = __half22float2(*(__half2*)&u.y);
        acc.x += a * fa.x; acc.y += a * fa.y; acc.z += a * fb.x; acc.w += a * fb.y;
    }
    ((float4*)(g_z + (size_t)b * E_))[e4] = acc;
}

// ---------------- GRU cell + masked h update -------------------------------
__global__ void k_gru(const int* __restrict__ lengths, int t) {
    int i = blockIdx.x * 256 + threadIdx.x;   // B*H
    int b = i / H_, j = i % H_;
    const float* gi = g_gi + b * 3 * H_;
    const float* gh = g_gh + b * 3 * H_;
    float r  = fsig(gi[j]        + gh[j]);
    float zg = fsig(gi[H_ + j]   + gh[H_ + j]);
    float n  = ftanh(gi[2*H_ + j] + r * gh[2*H_ + j]);
    float h  = g_h[i];
    float hn = (1.f - zg) * n + zg * h;
    if (lengths[b] - 1 >= t) g_h[i] = hn;
}

// ---------------- host driver ----------------------------------------------
extern "C" void kernel_launch(void* const* d_in, const int* in_sizes, int n_in,
                              void* d_out, int out_size) {
    const float* features  = (const float*)d_in[0];
    const int*   captions  = (const int*)  d_in[1];
    const int*   lengths   = (const int*)  d_in[2];
    const float* Wx_w      = (const float*)d_in[3];
    const float* Wx_b      = (const float*)d_in[4];
    const float* Wh_w      = (const float*)d_in[5];
    const float* Wh_b      = (const float*)d_in[6];
    const float* V_w       = (const float*)d_in[7];
    const float* V_b       = (const float*)d_in[8];
    const float* init_h_w  = (const float*)d_in[9];
    const float* init_h_b  = (const float*)d_in[10];
    const float* f_beta_w  = (const float*)d_in[11];
    const float* f_beta_b  = (const float*)d_in[12];
    const float* embed_w   = (const float*)d_in[13];
    const float* gru_w_ih  = (const float*)d_in[14];
    const float* gru_b_ih  = (const float*)d_in[15];
    const float* gru_w_hh  = (const float*)d_in[16];
    const float* gru_b_hh  = (const float*)d_in[17];
    const float* fc1_w     = (const float*)d_in[18];
    const float* fc1_b     = (const float*)d_in[19];
    float* out = (float*)d_out;

    __half *p_xwx;
    float *p_fmean, *p_h;
    cudaGetSymbolAddress((void**)&p_xwx,   g_xwx);
    cudaGetSymbolAddress((void**)&p_fmean, g_fmean);
    cudaGetSymbolAddress((void**)&p_h,     g_h);

    // zero outputs + write dec
    k_zero<<<2048, 256>>>(out, lengths);

    // fp16 copy of features (for k_z)
    k_feat16<<<(MP_*E_/4)/256, 256>>>(features);

    // h0 = mean_p(features) @ init_h_w^T + init_h_b
    k_fmean<<<(B_*E_/4)/256, 256>>>(features);
    k_gemm64<0><<<(H_ + 63)/64, 256>>>(p_fmean, init_h_w, init_h_b, p_h,
                                       H_, E_, H_, nullptr, 0);

    // x_wx = features @ Wx_w^T + Wx_b   (12544 x 2048 x 2048) -> fp16, tf32 TC
    k_gemm_tc<<<dim3(E_/128, MP_/128), 256>>>(features, Wx_w, Wx_b, p_xwx, E_, E_);

    for (int t = 0; t < TMAX; t++) {
        // h_wh + gate (fused, both A=h K=512 N=2048)
        k_step1<<<2*(E_/64), 256>>>(Wh_w, Wh_b, f_beta_w, f_beta_b);
        // attention scores
        k_lam<<<MP_, 256>>>(V_w, V_b);
        // softmax + z (fused; even block writes alphas)
        k_z<<<B_*2, 256>>>(out + PRED_SZ, lengths, t);
        // GRU gate GEMMs (fused gi+gh; inp built on the fly)
        k_gates<<<2*((3*H_)/64), 256>>>(gru_w_ih, gru_b_ih, gru_w_hh, gru_b_hh,
                                        embed_w, captions, t);
        k_gru<<<(B_*H_)/256, 256>>>(lengths, t);
        // pred = h_new @ fc1^T + b  -> preds[:, t, :] (masked; zeros pre-filled)
        k_gemm64<0><<<(V_ + 63)/64, 256>>>(p_h, fc1_w, fc1_b, out + (size_t)t * V_,
                                           V_, H_, TCAP * V_, lengths, t);
    }
}

// round 9
// speedup vs baseline: 1.9956x; 1.9956x over previous
#include <cuda_runtime.h>
#include <cuda_fp16.h>

#define B_    64
#define P_    196
#define E_    2048
#define H_    512
#define EMB_  512
#define V_    10000
#define TCAP  50
#define TMAX  49
#define MP_   (B_*P_)            /* 12544 */

#define PRED_SZ  ((size_t)B_*TCAP*V_)   /* 32,000,000 */
#define ALPHA_SZ ((size_t)B_*TCAP*P_)   /* 627,200 */

#define NB3H  ((3*H_)/64)        /* 24 N-blocks for the GRU gate GEMMs */
#define GI_SPLITS 4
#define GI_KCHUNK ((E_+EMB_)/GI_SPLITS)   /* 640 */

// ---------------- scratch (device globals; no allocation allowed) ----------
__device__ __half g_xwx[(size_t)MP_*E_];    // ~51.5 MB (fp16)
__device__ __half g_feat16[(size_t)MP_*E_]; // ~51.5 MB (fp16 copy of features)
__device__ float g_fmean[B_*E_];
__device__ float g_h[B_*H_];
__device__ float g_hwh[B_*E_];
__device__ float g_lam[B_*P_];
__device__ float g_z[B_*E_];
__device__ float g_gate[B_*E_];
__device__ float g_gip[GI_SPLITS][B_*3*H_];  // split-K partials for gi (no bias)
__device__ float g_gh[B_*3*H_];              // gh partial (no bias)

// ---------------- fast math ------------------------------------------------
__device__ __forceinline__ float ftanh(float x) {
    float y;
    asm("tanh.approx.f32 %0, %1;" : "=f"(y) : "f"(x));
    return y;
}
__device__ __forceinline__ float fsig(float x) {
    return 1.f / (1.f + __expf(-x));
}
__device__ __forceinline__ unsigned int f2tf32(float x) {
    unsigned int u;
    asm("cvt.rna.tf32.f32 %0, %1;" : "=r"(u) : "f"(x));
    return u;
}

// ---------------- zero output + write dec ----------------------------------
__global__ void k_zero(float* out, const int* lengths) {
    size_t n = PRED_SZ + ALPHA_SZ;
    size_t i = (size_t)blockIdx.x * blockDim.x + threadIdx.x;
    size_t stride = (size_t)gridDim.x * blockDim.x;
    for (size_t j = i; j < n; j += stride) out[j] = 0.f;
    if (i < B_) out[PRED_SZ + ALPHA_SZ + i] = (float)(lengths[i] - 1);
}

// ---------------- features -> fp16 copy ------------------------------------
__global__ void k_feat16(const float* __restrict__ feat) {
    size_t i = (size_t)blockIdx.x * 256 + threadIdx.x;   // over MP_*E_/4
    float4 v = ((const float4*)feat)[i];
    __half2 a = __floats2half2_rn(v.x, v.y);
    __half2 b = __floats2half2_rn(v.z, v.w);
    uint2 u;
    u.x = *(unsigned int*)&a;
    u.y = *(unsigned int*)&b;
    ((uint2*)g_feat16)[i] = u;
}

// ---------------- feature mean over P (float4) -----------------------------
__global__ void k_fmean(const float* __restrict__ feat) {
    int i = blockIdx.x * 256 + threadIdx.x;   // over B*E/4
    int b = i / (E_/4), e4 = i % (E_/4);
    const float4* fp = (const float4*)(feat + (size_t)b * P_ * E_) + e4;
    float4 s = make_float4(0.f, 0.f, 0.f, 0.f);
    #pragma unroll 4
    for (int p = 0; p < P_; p++) {
        float4 v = fp[(size_t)p * (E_/4)];
        s.x += v.x; s.y += v.y; s.z += v.z; s.w += v.w;
    }
    const float inv = 1.f / P_;
    s.x *= inv; s.y *= inv; s.z *= inv; s.w *= inv;
    ((float4*)g_fmean)[i] = s;
}

// ---------------- tf32 tensor-core GEMM: xwx(half) = A @ W^T + bias --------
__global__ void __launch_bounds__(256, 2)
k_gemm_tc(const float* __restrict__ A, const float* __restrict__ W,
          const float* __restrict__ bias, __half* __restrict__ C,
          int N, int K) {
    __shared__ __align__(16) float As[2][128][20];
    __shared__ __align__(16) float Ws[2][128][20];
    int tid = threadIdx.x;
    int m0 = blockIdx.y * 128, n0 = blockIdx.x * 128;
    int lr = tid >> 2;            // 0..63
    int lk = (tid & 3) * 4;       // 0,4,8,12
    int wid  = tid >> 5;          // 0..7
    int lane = tid & 31;
    int wm = wid & 1;
    int wn = wid >> 1;
    int g = lane >> 2, u = lane & 3;

    float acc[4][4][4] = {};

    #pragma unroll
    for (int r = 0; r < 2; r++) {
        int row = lr + r * 64;
        float4 v = *(const float4*)&A[(size_t)(m0 + row) * K + lk];
        As[0][row][lk+0] = __uint_as_float(f2tf32(v.x));
        As[0][row][lk+1] = __uint_as_float(f2tf32(v.y));
        As[0][row][lk+2] = __uint_as_float(f2tf32(v.z));
        As[0][row][lk+3] = __uint_as_float(f2tf32(v.w));
        float4 w = *(const float4*)&W[(size_t)(n0 + row) * K + lk];
        Ws[0][row][lk+0] = __uint_as_float(f2tf32(w.x));
        Ws[0][row][lk+1] = __uint_as_float(f2tf32(w.y));
        Ws[0][row][lk+2] = __uint_as_float(f2tf32(w.z));
        Ws[0][row][lk+3] = __uint_as_float(f2tf32(w.w));
    }
    __syncthreads();

    int buf = 0;
    for (int k0 = 0; k0 < K; k0 += 16) {
        bool more = (k0 + 16) < K;
        float4 pv[2], pw[2];
        if (more) {
            #pragma unroll
            for (int r = 0; r < 2; r++) {
                int row = lr + r * 64;
                pv[r] = *(const float4*)&A[(size_t)(m0 + row) * K + k0 + 16 + lk];
                pw[r] = *(const float4*)&W[(size_t)(n0 + row) * K + k0 + 16 + lk];
            }
        }
        #pragma unroll
        for (int ks = 0; ks < 16; ks += 8) {
            unsigned int af[4][4], bf[4][2];
            #pragma unroll
            for (int mt = 0; mt < 4; mt++) {
                int mb = wm * 64 + mt * 16;
                af[mt][0] = __float_as_uint(As[buf][mb + g    ][ks + u    ]);
                af[mt][1] = __float_as_uint(As[buf][mb + g + 8][ks + u    ]);
                af[mt][2] = __float_as_uint(As[buf][mb + g    ][ks + u + 4]);
                af[mt][3] = __float_as_uint(As[buf][mb + g + 8][ks + u + 4]);
            }
            #pragma unroll
            for (int nt = 0; nt < 4; nt++) {
                int nb = wn * 32 + nt * 8;
                bf[nt][0] = __float_as_uint(Ws[buf][nb + g][ks + u    ]);
                bf[nt][1] = __float_as_uint(Ws[buf][nb + g][ks + u + 4]);
            }
            #pragma unroll
            for (int mt = 0; mt < 4; mt++)
                #pragma unroll
                for (int nt = 0; nt < 4; nt++) {
                    asm volatile(
                        "mma.sync.aligned.m16n8k8.row.col.f32.tf32.tf32.f32 "
                        "{%0,%1,%2,%3}, {%4,%5,%6,%7}, {%8,%9}, {%0,%1,%2,%3};"
                        : "+f"(acc[mt][nt][0]), "+f"(acc[mt][nt][1]),
                          "+f"(acc[mt][nt][2]), "+f"(acc[mt][nt][3])
                        : "r"(af[mt][0]), "r"(af[mt][1]), "r"(af[mt][2]), "r"(af[mt][3]),
                          "r"(bf[nt][0]), "r"(bf[nt][1]));
                }
        }
        if (more) {
            int nb = buf ^ 1;
            #pragma unroll
            for (int r = 0; r < 2; r++) {
                int row = lr + r * 64;
                As[nb][row][lk+0] = __uint_as_float(f2tf32(pv[r].x));
                As[nb][row][lk+1] = __uint_as_float(f2tf32(pv[r].y));
                As[nb][row][lk+2] = __uint_as_float(f2tf32(pv[r].z));
                As[nb][row][lk+3] = __uint_as_float(f2tf32(pv[r].w));
                Ws[nb][row][lk+0] = __uint_as_float(f2tf32(pw[r].x));
                Ws[nb][row][lk+1] = __uint_as_float(f2tf32(pw[r].y));
                Ws[nb][row][lk+2] = __uint_as_float(f2tf32(pw[r].z));
                Ws[nb][row][lk+3] = __uint_as_float(f2tf32(pw[r].w));
            }
            __syncthreads();
            buf = nb;
        }
    }

    #pragma unroll
    for (int mt = 0; mt < 4; mt++) {
        #pragma unroll
        for (int nt = 0; nt < 4; nt++) {
            int m = m0 + wm * 64 + mt * 16 + g;
            int n = n0 + wn * 32 + nt * 8 + u * 2;
            float b0 = bias[n], b1 = bias[n + 1];
            __half2 h0 = __floats2half2_rn(acc[mt][nt][0] + b0, acc[mt][nt][1] + b1);
            *(__half2*)&C[(size_t)m * N + n] = h0;
            __half2 h1 = __floats2half2_rn(acc[mt][nt][2] + b0, acc[mt][nt][3] + b1);
            *(__half2*)&C[(size_t)(m + 8) * N + n] = h1;
        }
    }
}

// ---------------- inner compute for skinny GEMMs (float4 smem reads) -------
__device__ __forceinline__ void mm_tile32(const float (*As)[68], const float (*Ws)[68],
                                          int ty, int tx, float acc[4][4]) {
    #pragma unroll
    for (int kk = 0; kk < 32; kk++) {
        float4 a4 = *(const float4*)&As[kk][ty*4];
        float4 b4 = *(const float4*)&Ws[kk][tx*4];
        float a[4] = {a4.x, a4.y, a4.z, a4.w};
        float b[4] = {b4.x, b4.y, b4.z, b4.w};
        #pragma unroll
        for (int i = 0; i < 4; i++)
            #pragma unroll
            for (int j = 0; j < 4; j++)
                acc[i][j] += a[i] * b[j];
    }
}

// ---------------- skinny GEMM: M fixed 64, prefetch double-buffered --------
template<int ACT>   // 0 = none, 1 = sigmoid
__global__ void k_gemm64(const float* __restrict__ A, const float* __restrict__ W,
                         const float* __restrict__ bias, float* __restrict__ C,
                         int N, int K, int ldc, const int* __restrict__ lengths, int t) {
    __shared__ __align__(16) float As[2][32][68];
    __shared__ __align__(16) float Ws[2][32][68];
    int tid = threadIdx.x;
    int n0 = blockIdx.x * 64;
    int lr = tid >> 3, lk = (tid & 7) * 4;
    int ty = tid >> 4, tx = tid & 15;
    float acc[4][4] = {};
    float4 va[2], vw[2];
    #pragma unroll
    for (int r = 0; r < 2; r++) {
        int row = lr + r * 32;
        va[r] = *(const float4*)&A[(size_t)row * K + lk];
        int wn = n0 + row;
        vw[r] = (wn < N) ? *(const float4*)&W[(size_t)wn * K + lk] : make_float4(0.f,0.f,0.f,0.f);
    }
    #pragma unroll
    for (int r = 0; r < 2; r++) {
        int row = lr + r * 32;
        As[0][lk+0][row]=va[r].x; As[0][lk+1][row]=va[r].y; As[0][lk+2][row]=va[r].z; As[0][lk+3][row]=va[r].w;
        Ws[0][lk+0][row]=vw[r].x; Ws[0][lk+1][row]=vw[r].y; Ws[0][lk+2][row]=vw[r].z; Ws[0][lk+3][row]=vw[r].w;
    }
    __syncthreads();
    int buf = 0;
    for (int k0 = 0; k0 < K; k0 += 32) {
        bool more = (k0 + 32) < K;
        if (more) {
            #pragma unroll
            for (int r = 0; r < 2; r++) {
                int row = lr + r * 32;
                va[r] = *(const float4*)&A[(size_t)row * K + k0 + 32 + lk];
                int wn = n0 + row;
                vw[r] = (wn < N) ? *(const float4*)&W[(size_t)wn * K + k0 + 32 + lk] : make_float4(0.f,0.f,0.f,0.f);
            }
        }
        mm_tile32(As[buf], Ws[buf], ty, tx, acc);
        if (more) {
            buf ^= 1;
            #pragma unroll
            for (int r = 0; r < 2; r++) {
                int row = lr + r * 32;
                As[buf][lk+0][row]=va[r].x; As[buf][lk+1][row]=va[r].y; As[buf][lk+2][row]=va[r].z; As[buf][lk+3][row]=va[r].w;
                Ws[buf][lk+0][row]=vw[r].x; Ws[buf][lk+1][row]=vw[r].y; Ws[buf][lk+2][row]=vw[r].z; Ws[buf][lk+3][row]=vw[r].w;
            }
            __syncthreads();
        }
    }
    #pragma unroll
    for (int i = 0; i < 4; i++) {
        int b = ty*4 + i;
        if (lengths && (lengths[b] - 1 < t)) continue;
        #pragma unroll
        for (int j = 0; j < 4; j++) {
            int n = n0 + tx*4 + j;
            if (n < N) {
                float v = acc[i][j] + bias[n];
                if (ACT == 1) v = fsig(v);
                C[(size_t)b * ldc + n] = v;
            }
        }
    }
}

// ---------------- fused step GEMM 1: h_wh (0..31) + gate (32..63) ----------
__global__ void k_step1(const float* __restrict__ Wh_w, const float* __restrict__ Wh_b,
                        const float* __restrict__ fb_w, const float* __restrict__ fb_b) {
    bool sig = blockIdx.x >= (E_/64);
    int n0 = (sig ? blockIdx.x - E_/64 : blockIdx.x) * 64;
    const float* W    = sig ? fb_w : Wh_w;
    const float* bias = sig ? fb_b : Wh_b;
    float* C          = sig ? g_gate : g_hwh;
    __shared__ __align__(16) float As[2][32][68];
    __shared__ __align__(16) float Ws[2][32][68];
    int tid = threadIdx.x;
    int lr = tid >> 3, lk = (tid & 7) * 4;
    int ty = tid >> 4, tx = tid & 15;
    float acc[4][4] = {};
    float4 va[2], vw[2];
    #pragma unroll
    for (int r = 0; r < 2; r++) {
        int row = lr + r * 32;
        va[r] = *(const float4*)&g_h[(size_t)row * H_ + lk];
        vw[r] = *(const float4*)&W[(size_t)(n0 + row) * H_ + lk];
    }
    #pragma unroll
    for (int r = 0; r < 2; r++) {
        int row = lr + r * 32;
        As[0][lk+0][row]=va[r].x; As[0][lk+1][row]=va[r].y; As[0][lk+2][row]=va[r].z; As[0][lk+3][row]=va[r].w;
        Ws[0][lk+0][row]=vw[r].x; Ws[0][lk+1][row]=vw[r].y; Ws[0][lk+2][row]=vw[r].z; Ws[0][lk+3][row]=vw[r].w;
    }
    __syncthreads();
    int buf = 0;
    for (int k0 = 0; k0 < H_; k0 += 32) {
        bool more = (k0 + 32) < H_;
        if (more) {
            #pragma unroll
            for (int r = 0; r < 2; r++) {
                int row = lr + r * 32;
                va[r] = *(const float4*)&g_h[(size_t)row * H_ + k0 + 32 + lk];
                vw[r] = *(const float4*)&W[(size_t)(n0 + row) * H_ + k0 + 32 + lk];
            }
        }
        mm_tile32(As[buf], Ws[buf], ty, tx, acc);
        if (more) {
            buf ^= 1;
            #pragma unroll
            for (int r = 0; r < 2; r++) {
                int row = lr + r * 32;
                As[buf][lk+0][row]=va[r].x; As[buf][lk+1][row]=va[r].y; As[buf][lk+2][row]=va[r].z; As[buf][lk+3][row]=va[r].w;
                Ws[buf][lk+0][row]=vw[r].x; Ws[buf][lk+1][row]=vw[r].y; Ws[buf][lk+2][row]=vw[r].z; Ws[buf][lk+3][row]=vw[r].w;
            }
            __syncthreads();
        }
    }
    #pragma unroll
    for (int i = 0; i < 4; i++) {
        int b = ty*4 + i;
        #pragma unroll
        for (int j = 0; j < 4; j++) {
            int n = n0 + tx*4 + j;
            float v = acc[i][j] + bias[n];
            if (sig) v = fsig(v);
            C[(size_t)b * E_ + n] = v;
        }
    }
}

// ---------------- GRU gate GEMMs: gi split-K x4 + gh ------------------------
// blocks 0..95: gi split s = blk/NB3H, n0 = (blk%NB3H)*64, K chunk 640 -> g_gip[s]
// blocks 96..119: gh, K = 512 -> g_gh. No bias here (added in k_gru).
__global__ void k_gates(const float* __restrict__ w_ih, const float* __restrict__ w_hh,
                        const float* __restrict__ embed, const int* __restrict__ captions,
                        int t) {
    int blk = blockIdx.x;
    bool is_gi = blk < NB3H * GI_SPLITS;
    int s     = is_gi ? (blk / NB3H) : 0;
    int n0    = (is_gi ? (blk % NB3H) : (blk - NB3H * GI_SPLITS)) * 64;
    int kbase = is_gi ? s * GI_KCHUNK : 0;
    int Klen  = is_gi ? GI_KCHUNK : H_;
    int Kfull = is_gi ? (E_ + EMB_) : H_;
    const float* W = is_gi ? w_ih : w_hh;
    float* C       = is_gi ? g_gip[s] : g_gh;

    __shared__ __align__(16) float As[2][32][68];
    __shared__ __align__(16) float Ws[2][32][68];
    int tid = threadIdx.x;
    int lr = tid >> 3, lk = (tid & 7) * 4;
    int ty = tid >> 4, tx = tid & 15;
    float acc[4][4] = {};
    float4 va[2], vw[2];

    #define FETCH_A(row, kg, dst) do {                                            \
        if (is_gi) {                                                              \
            if ((kg) < E_) {                                                      \
                float4 gg = *(const float4*)&g_gate[(size_t)(row) * E_ + (kg)];   \
                float4 zz = *(const float4*)&g_z[(size_t)(row) * E_ + (kg)];      \
                dst = make_float4(gg.x*zz.x, gg.y*zz.y, gg.z*zz.z, gg.w*zz.w);    \
            } else {                                                              \
                int cap = captions[(row) * TCAP + t];                             \
                dst = *(const float4*)&embed[(size_t)cap * EMB_ + ((kg) - E_)];   \
            }                                                                     \
        } else {                                                                  \
            dst = *(const float4*)&g_h[(size_t)(row) * H_ + (kg)];                \
        }                                                                         \
    } while (0)

    #pragma unroll
    for (int r = 0; r < 2; r++) {
        int row = lr + r * 32;
        FETCH_A(row, kbase + lk, va[r]);
        vw[r] = *(const float4*)&W[(size_t)(n0 + row) * Kfull + kbase + lk];
    }
    #pragma unroll
    for (int r = 0; r < 2; r++) {
        int row = lr + r * 32;
        As[0][lk+0][row]=va[r].x; As[0][lk+1][row]=va[r].y; As[0][lk+2][row]=va[r].z; As[0][lk+3][row]=va[r].w;
        Ws[0][lk+0][row]=vw[r].x; Ws[0][lk+1][row]=vw[r].y; Ws[0][lk+2][row]=vw[r].z; Ws[0][lk+3][row]=vw[r].w;
    }
    __syncthreads();
    int buf = 0;
    for (int k0 = 0; k0 < Klen; k0 += 32) {
        bool more = (k0 + 32) < Klen;
        if (more) {
            #pragma unroll
            for (int r = 0; r < 2; r++) {
                int row = lr + r * 32;
                int kg = kbase + k0 + 32 + lk;
                FETCH_A(row, kg, va[r]);
                vw[r] = *(const float4*)&W[(size_t)(n0 + row) * Kfull + kg];
            }
        }
        mm_tile32(As[buf], Ws[buf], ty, tx, acc);
        if (more) {
            buf ^= 1;
            #pragma unroll
            for (int r = 0; r < 2; r++) {
                int row = lr + r * 32;
                As[buf][lk+0][row]=va[r].x; As[buf][lk+1][row]=va[r].y; As[buf][lk+2][row]=va[r].z; As[buf][lk+3][row]=va[r].w;
                Ws[buf][lk+0][row]=vw[r].x; Ws[buf][lk+1][row]=vw[r].y; Ws[buf][lk+2][row]=vw[r].z; Ws[buf][lk+3][row]=vw[r].w;
            }
            __syncthreads();
        }
    }
    #undef FETCH_A
    #pragma unroll
    for (int i = 0; i < 4; i++) {
        int b = ty*4 + i;
        #pragma unroll
        for (int j = 0; j < 4; j++) {
            int n = n0 + tx*4 + j;
            C[(size_t)b * (3*H_) + n] = acc[i][j];
        }
    }
}

// ---------------- attention: lam[b,p] = V . tanh(xwx16[b,p]+h_wh[b]) + Vb --
__global__ void k_lam(const float* __restrict__ Vw, const float* __restrict__ Vb) {
    int bp = blockIdx.x;
    int b  = bp / P_;
    int tid = threadIdx.x;
    const uint2*  xw2 = (const uint2*)(g_xwx + (size_t)bp * E_);
    const float4* hw4 = (const float4*)(g_hwh + (size_t)b * E_);
    const float4* vw4 = (const float4*)Vw;
    float s = 0.f;
    #pragma unroll
    for (int q = 0; q < 2; q++) {
        int i = tid * 2 + q;
        uint2 u = xw2[i];
        float2 fa = __half22float2(*(__half2*)&u.x);
        float2 fb = __half22float2(*(__half2*)&u.y);
        float4 h = hw4[i];
        float4 v = vw4[i];
        s += ftanh(fa.x + h.x) * v.x + ftanh(fa.y + h.y) * v.y
           + ftanh(fb.x + h.z) * v.z + ftanh(fb.y + h.w) * v.w;
    }
    __shared__ float red[8];
    int lane = tid & 31, w = tid >> 5;
    #pragma unroll
    for (int o = 16; o > 0; o >>= 1) s += __shfl_xor_sync(0xffffffffu, s, o);
    if (lane == 0) red[w] = s;
    __syncthreads();
    if (tid == 0) {
        float tot = 0.f;
        #pragma unroll
        for (int i = 0; i < 8; i++) tot += red[i];
        g_lam[bp] = tot + Vb[0];
    }
}

// ---------------- fused softmax + z ----------------------------------------
__global__ void k_z(float* __restrict__ out_alphas, const int* __restrict__ lengths, int t) {
    int b  = blockIdx.x >> 1;
    int tid = threadIdx.x;
    int lane = tid & 31, w = tid >> 5;
    __shared__ float red[8];
    __shared__ float bmax, bsum;
    __shared__ float al[P_];

    float v = (tid < P_) ? g_lam[b * P_ + tid] : -3.4e38f;
    float m = v;
    #pragma unroll
    for (int o = 16; o > 0; o >>= 1) m = fmaxf(m, __shfl_xor_sync(0xffffffffu, m, o));
    if (lane == 0) red[w] = m;
    __syncthreads();
    if (tid == 0) {
        float mm = red[0];
        #pragma unroll
        for (int i = 1; i < 8; i++) mm = fmaxf(mm, red[i]);
        bmax = mm;
    }
    __syncthreads();
    float ex = (tid < P_) ? __expf(v - bmax) : 0.f;
    float s = ex;
    #pragma unroll
    for (int o = 16; o > 0; o >>= 1) s += __shfl_xor_sync(0xffffffffu, s, o);
    if (lane == 0) red[w] = s;
    __syncthreads();
    if (tid == 0) {
        float ss = 0.f;
        #pragma unroll
        for (int i = 0; i < 8; i++) ss += red[i];
        bsum = ss;
    }
    __syncthreads();
    if (tid < P_) {
        float a = ex / bsum;
        al[tid] = a;
        if (((blockIdx.x & 1) == 0) && (lengths[b] - 1 >= t))
            out_alphas[(size_t)b * TCAP * P_ + (size_t)t * P_ + tid] = a;
    }
    __syncthreads();

    int e4 = ((blockIdx.x & 1) << 8) + tid;
    const uint2* fp = (const uint2*)(g_feat16 + (size_t)b * P_ * E_) + e4;
    float4 acc = make_float4(0.f, 0.f, 0.f, 0.f);
    #pragma unroll 4
    for (int p = 0; p < P_; p++) {
        float a = al[p];
        uint2 u = fp[(size_t)p * (E_/4)];
        float2 fa = __half22float2(*(__half2*)&u.x);
        float2 fb = __half22float2(*(__half2*)&u.y);
        acc.x += a * fa.x; acc.y += a * fa.y; acc.z += a * fb.x; acc.w += a * fb.y;
    }
    ((float4*)(g_z + (size_t)b * E_))[e4] = acc;
}

// ---------------- GRU cell: sum split parts + biases + masked h update -----
__global__ void k_gru(const float* __restrict__ b_ih, const float* __restrict__ b_hh,
                      const int* __restrict__ lengths, int t) {
    int i = blockIdx.x * 256 + threadIdx.x;   // B*H
    int b = i / H_, j = i % H_;
    size_t base = (size_t)b * 3 * H_;
    float gi_r = b_ih[j],        gi_z = b_ih[H_ + j],        gi_n = b_ih[2*H_ + j];
    #pragma unroll
    for (int s = 0; s < GI_SPLITS; s++) {
        gi_r += g_gip[s][base + j];
        gi_z += g_gip[s][base + H_ + j];
        gi_n += g_gip[s][base + 2*H_ + j];
    }
    float gh_r = g_gh[base + j]        + b_hh[j];
    float gh_z = g_gh[base + H_ + j]   + b_hh[H_ + j];
    float gh_n = g_gh[base + 2*H_ + j] + b_hh[2*H_ + j];
    float r  = fsig(gi_r + gh_r);
    float zg = fsig(gi_z + gh_z);
    float n  = ftanh(gi_n + r * gh_n);
    float h  = g_h[i];
    float hn = (1.f - zg) * n + zg * h;
    if (lengths[b] - 1 >= t) g_h[i] = hn;
}

// ---------------- host driver ----------------------------------------------
extern "C" void kernel_launch(void* const* d_in, const int* in_sizes, int n_in,
                              void* d_out, int out_size) {
    const float* features  = (const float*)d_in[0];
    const int*   captions  = (const int*)  d_in[1];
    const int*   lengths   = (const int*)  d_in[2];
    const float* Wx_w      = (const float*)d_in[3];
    const float* Wx_b      = (const float*)d_in[4];
    const float* Wh_w      = (const float*)d_in[5];
    const float* Wh_b      = (const float*)d_in[6];
    const float* V_w       = (const float*)d_in[7];
    const float* V_b       = (const float*)d_in[8];
    const float* init_h_w  = (const float*)d_in[9];
    const float* init_h_b  = (const float*)d_in[10];
    const float* f_beta_w  = (const float*)d_in[11];
    const float* f_beta_b  = (const float*)d_in[12];
    const float* embed_w   = (const float*)d_in[13];
    const float* gru_w_ih  = (const float*)d_in[14];
    const float* gru_b_ih  = (const float*)d_in[15];
    const float* gru_w_hh  = (const float*)d_in[16];
    const float* gru_b_hh  = (const float*)d_in[17];
    const float* fc1_w     = (const float*)d_in[18];
    const float* fc1_b     = (const float*)d_in[19];
    float* out = (float*)d_out;

    __half *p_xwx;
    float *p_fmean, *p_h;
    cudaGetSymbolAddress((void**)&p_xwx,   g_xwx);
    cudaGetSymbolAddress((void**)&p_fmean, g_fmean);
    cudaGetSymbolAddress((void**)&p_h,     g_h);

    k_zero<<<2048, 256>>>(out, lengths);
    k_feat16<<<(MP_*E_/4)/256, 256>>>(features);
    k_fmean<<<(B_*E_/4)/256, 256>>>(features);
    k_gemm64<0><<<(H_ + 63)/64, 256>>>(p_fmean, init_h_w, init_h_b, p_h,
                                       H_, E_, H_, nullptr, 0);
    k_gemm_tc<<<dim3(E_/128, MP_/128), 256>>>(features, Wx_w, Wx_b, p_xwx, E_, E_);

    for (int t = 0; t < TMAX; t++) {
        k_step1<<<2*(E_/64), 256>>>(Wh_w, Wh_b, f_beta_w, f_beta_b);
        k_lam<<<MP_, 256>>>(V_w, V_b);
        k_z<<<B_*2, 256>>>(out + PRED_SZ, lengths, t);
        k_gates<<<NB3H*GI_SPLITS + NB3H, 256>>>(gru_w_ih, gru_w_hh, embed_w, captions, t);
        k_gru<<<(B_*H_)/256, 256>>>(gru_b_ih, gru_b_hh, lengths, t);
        k_gemm64<0><<<(V_ + 63)/64, 256>>>(p_h, fc1_w, fc1_b, out + (size_t)t * V_,
                                           V_, H_, TCAP * V_, lengths, t);
    }
}

// round 10
// speedup vs baseline: 2.5098x; 1.2576x over previous
#include <cuda_runtime.h>
#include <cuda_fp16.h>

#define B_    64
#define P_    196
#define E_    2048
#define H_    512
#define EMB_  512
#define V_    10000
#define TCAP  50
#define TMAX  49
#define MP_   (B_*P_)            /* 12544 */

#define PRED_SZ  ((size_t)B_*TCAP*V_)   /* 32,000,000 */
#define ALPHA_SZ ((size_t)B_*TCAP*P_)   /* 627,200 */

#define NB3H  ((3*H_)/64)        /* 24 N-blocks (64 cols) for GRU gate GEMMs */
#define GI_SPLITS 4
#define GI_KCHUNK ((E_+EMB_)/GI_SPLITS)   /* 640 */

// ---------------- scratch (device globals; no allocation allowed) ----------
__device__ __half g_xwx[(size_t)MP_*E_];    // ~51.5 MB (fp16)
__device__ __half g_feat16[(size_t)MP_*E_]; // ~51.5 MB (fp16 copy of features)
__device__ float g_fmean[B_*E_];
__device__ float g_h[B_*H_];
__device__ float g_hwh[B_*E_];
__device__ float g_lam[B_*P_];
__device__ float g_z[B_*E_];
__device__ float g_gate[B_*E_];
__device__ float g_gip[GI_SPLITS][B_*3*H_];  // split-K partials for gi (no bias)
__device__ float g_gh[B_*3*H_];              // gh partial (no bias)

// ---------------- fast math ------------------------------------------------
__device__ __forceinline__ float ftanh(float x) {
    float y;
    asm("tanh.approx.f32 %0, %1;" : "=f"(y) : "f"(x));
    return y;
}
__device__ __forceinline__ float fsig(float x) {
    return 1.f / (1.f + __expf(-x));
}
__device__ __forceinline__ unsigned int f2tf32(float x) {
    unsigned int u;
    asm("cvt.rna.tf32.f32 %0, %1;" : "=r"(u) : "f"(x));
    return u;
}
__device__ __forceinline__ float4 tf32x4(float4 v) {
    v.x = __uint_as_float(f2tf32(v.x));
    v.y = __uint_as_float(f2tf32(v.y));
    v.z = __uint_as_float(f2tf32(v.z));
    v.w = __uint_as_float(f2tf32(v.w));
    return v;
}
#define MMA_TF32(acc, af, bf)                                                  \
    asm volatile(                                                              \
        "mma.sync.aligned.m16n8k8.row.col.f32.tf32.tf32.f32 "                  \
        "{%0,%1,%2,%3}, {%4,%5,%6,%7}, {%8,%9}, {%0,%1,%2,%3};"                \
        : "+f"((acc)[0]), "+f"((acc)[1]), "+f"((acc)[2]), "+f"((acc)[3])       \
        : "r"((af)[0]), "r"((af)[1]), "r"((af)[2]), "r"((af)[3]),              \
          "r"((bf)[0]), "r"((bf)[1]))

// ---------------- zero output + write dec ----------------------------------
__global__ void k_zero(float* out, const int* lengths) {
    size_t n = PRED_SZ + ALPHA_SZ;
    size_t i = (size_t)blockIdx.x * blockDim.x + threadIdx.x;
    size_t stride = (size_t)gridDim.x * blockDim.x;
    for (size_t j = i; j < n; j += stride) out[j] = 0.f;
    if (i < B_) out[PRED_SZ + ALPHA_SZ + i] = (float)(lengths[i] - 1);
}

// ---------------- features -> fp16 copy ------------------------------------
__global__ void k_feat16(const float* __restrict__ feat) {
    size_t i = (size_t)blockIdx.x * 256 + threadIdx.x;   // over MP_*E_/4
    float4 v = ((const float4*)feat)[i];
    __half2 a = __floats2half2_rn(v.x, v.y);
    __half2 b = __floats2half2_rn(v.z, v.w);
    uint2 u;
    u.x = *(unsigned int*)&a;
    u.y = *(unsigned int*)&b;
    ((uint2*)g_feat16)[i] = u;
}

// ---------------- feature mean over P (float4) -----------------------------
__global__ void k_fmean(const float* __restrict__ feat) {
    int i = blockIdx.x * 256 + threadIdx.x;   // over B*E/4
    int b = i / (E_/4), e4 = i % (E_/4);
    const float4* fp = (const float4*)(feat + (size_t)b * P_ * E_) + e4;
    float4 s = make_float4(0.f, 0.f, 0.f, 0.f);
    #pragma unroll 4
    for (int p = 0; p < P_; p++) {
        float4 v = fp[(size_t)p * (E_/4)];
        s.x += v.x; s.y += v.y; s.z += v.z; s.w += v.w;
    }
    const float inv = 1.f / P_;
    s.x *= inv; s.y *= inv; s.z *= inv; s.w *= inv;
    ((float4*)g_fmean)[i] = s;
}

// ---------------- tf32 tensor-core GEMM: xwx(half) = A @ W^T + bias --------
// 128x128 tile, BK=16, 8 warps (2M x 4N), warp tile 64x32. (unchanged, proven)
__global__ void __launch_bounds__(256, 2)
k_gemm_tc(const float* __restrict__ A, const float* __restrict__ W,
          const float* __restrict__ bias, __half* __restrict__ C,
          int N, int K) {
    __shared__ __align__(16) float As[2][128][20];
    __shared__ __align__(16) float Ws[2][128][20];
    int tid = threadIdx.x;
    int m0 = blockIdx.y * 128, n0 = blockIdx.x * 128;
    int lr = tid >> 2;
    int lk = (tid & 3) * 4;
    int wid  = tid >> 5;
    int lane = tid & 31;
    int wm = wid & 1;
    int wn = wid >> 1;
    int g = lane >> 2, u = lane & 3;

    float acc[4][4][4] = {};

    #pragma unroll
    for (int r = 0; r < 2; r++) {
        int row = lr + r * 64;
        float4 v = tf32x4(*(const float4*)&A[(size_t)(m0 + row) * K + lk]);
        As[0][row][lk+0] = v.x; As[0][row][lk+1] = v.y; As[0][row][lk+2] = v.z; As[0][row][lk+3] = v.w;
        float4 w = tf32x4(*(const float4*)&W[(size_t)(n0 + row) * K + lk]);
        Ws[0][row][lk+0] = w.x; Ws[0][row][lk+1] = w.y; Ws[0][row][lk+2] = w.z; Ws[0][row][lk+3] = w.w;
    }
    __syncthreads();

    int buf = 0;
    for (int k0 = 0; k0 < K; k0 += 16) {
        bool more = (k0 + 16) < K;
        float4 pv[2], pw[2];
        if (more) {
            #pragma unroll
            for (int r = 0; r < 2; r++) {
                int row = lr + r * 64;
                pv[r] = *(const float4*)&A[(size_t)(m0 + row) * K + k0 + 16 + lk];
                pw[r] = *(const float4*)&W[(size_t)(n0 + row) * K + k0 + 16 + lk];
            }
        }
        #pragma unroll
        for (int ks = 0; ks < 16; ks += 8) {
            unsigned int af[4][4], bf[4][2];
            #pragma unroll
            for (int mt = 0; mt < 4; mt++) {
                int mb = wm * 64 + mt * 16;
                af[mt][0] = __float_as_uint(As[buf][mb + g    ][ks + u    ]);
                af[mt][1] = __float_as_uint(As[buf][mb + g + 8][ks + u    ]);
                af[mt][2] = __float_as_uint(As[buf][mb + g    ][ks + u + 4]);
                af[mt][3] = __float_as_uint(As[buf][mb + g + 8][ks + u + 4]);
            }
            #pragma unroll
            for (int nt = 0; nt < 4; nt++) {
                int nb = wn * 32 + nt * 8;
                bf[nt][0] = __float_as_uint(Ws[buf][nb + g][ks + u    ]);
                bf[nt][1] = __float_as_uint(Ws[buf][nb + g][ks + u + 4]);
            }
            #pragma unroll
            for (int mt = 0; mt < 4; mt++)
                #pragma unroll
                for (int nt = 0; nt < 4; nt++)
                    MMA_TF32(acc[mt][nt], af[mt], bf[nt]);
        }
        if (more) {
            int nb = buf ^ 1;
            #pragma unroll
            for (int r = 0; r < 2; r++) {
                int row = lr + r * 64;
                float4 v = tf32x4(pv[r]);
                As[nb][row][lk+0] = v.x; As[nb][row][lk+1] = v.y; As[nb][row][lk+2] = v.z; As[nb][row][lk+3] = v.w;
                float4 w = tf32x4(pw[r]);
                Ws[nb][row][lk+0] = w.x; Ws[nb][row][lk+1] = w.y; Ws[nb][row][lk+2] = w.z; Ws[nb][row][lk+3] = w.w;
            }
            __syncthreads();
            buf = nb;
        }
    }

    #pragma unroll
    for (int mt = 0; mt < 4; mt++) {
        #pragma unroll
        for (int nt = 0; nt < 4; nt++) {
            int m = m0 + wm * 64 + mt * 16 + g;
            int n = n0 + wn * 32 + nt * 8 + u * 2;
            float b0 = bias[n], b1 = bias[n + 1];
            __half2 h0 = __floats2half2_rn(acc[mt][nt][0] + b0, acc[mt][nt][1] + b1);
            *(__half2*)&C[(size_t)m * N + n] = h0;
            __half2 h1 = __floats2half2_rn(acc[mt][nt][2] + b0, acc[mt][nt][3] + b1);
            *(__half2*)&C[(size_t)(m + 8) * N + n] = h1;
        }
    }
}

// ---------------- tf32 TC skinny GEMM: M=64 fixed, N-tile 64, BK=32 --------
// 8 warps as 2(M)x4(N); warp tile 32x16 (mt2 x nt2). act: 0 none, 1 sigmoid.
// lengths!=null masks output rows (batch m) where lengths[m]-1 < t.
__global__ void __launch_bounds__(256)
k_tc64(const float* __restrict__ A, const float* __restrict__ W,
       const float* __restrict__ bias, float* __restrict__ C,
       int N, int K, int ldc, int act,
       const int* __restrict__ lengths, int t) {
    __shared__ __align__(16) float As[2][64][36];
    __shared__ __align__(16) float Ws[2][64][36];
    int tid = threadIdx.x;
    int n0 = blockIdx.x * 64;
    int row = tid >> 2;            // 0..63
    int lk8 = (tid & 3) * 8;       // 0,8,16,24
    int wid = tid >> 5, lane = tid & 31;
    int wm = wid & 1, wn = wid >> 1;
    int g = lane >> 2, u = lane & 3;
    int wrow = n0 + row; if (wrow >= N) wrow = N - 1;   // clamp (pred tail)

    float acc[2][2][4] = {};
    float4 pa0, pa1, pw0, pw1;

    pa0 = *(const float4*)&A[(size_t)row * K + lk8];
    pa1 = *(const float4*)&A[(size_t)row * K + lk8 + 4];
    pw0 = *(const float4*)&W[(size_t)wrow * K + lk8];
    pw1 = *(const float4*)&W[(size_t)wrow * K + lk8 + 4];
    *(float4*)&As[0][row][lk8]     = tf32x4(pa0);
    *(float4*)&As[0][row][lk8 + 4] = tf32x4(pa1);
    *(float4*)&Ws[0][row][lk8]     = tf32x4(pw0);
    *(float4*)&Ws[0][row][lk8 + 4] = tf32x4(pw1);
    __syncthreads();

    int buf = 0;
    for (int k0 = 0; k0 < K; k0 += 32) {
        bool more = (k0 + 32) < K;
        if (more) {
            pa0 = *(const float4*)&A[(size_t)row * K + k0 + 32 + lk8];
            pa1 = *(const float4*)&A[(size_t)row * K + k0 + 32 + lk8 + 4];
            pw0 = *(const float4*)&W[(size_t)wrow * K + k0 + 32 + lk8];
            pw1 = *(const float4*)&W[(size_t)wrow * K + k0 + 32 + lk8 + 4];
        }
        #pragma unroll
        for (int ks = 0; ks < 32; ks += 8) {
            unsigned int af[2][4], bf[2][2];
            #pragma unroll
            for (int mt = 0; mt < 2; mt++) {
                int mb = wm * 32 + mt * 16;
                af[mt][0] = __float_as_uint(As[buf][mb + g    ][ks + u    ]);
                af[mt][1] = __float_as_uint(As[buf][mb + g + 8][ks + u    ]);
                af[mt][2] = __float_as_uint(As[buf][mb + g    ][ks + u + 4]);
                af[mt][3] = __float_as_uint(As[buf][mb + g + 8][ks + u + 4]);
            }
            #pragma unroll
            for (int nt = 0; nt < 2; nt++) {
                int nb = wn * 16 + nt * 8;
                bf[nt][0] = __float_as_uint(Ws[buf][nb + g][ks + u    ]);
                bf[nt][1] = __float_as_uint(Ws[buf][nb + g][ks + u + 4]);
            }
            #pragma unroll
            for (int mt = 0; mt < 2; mt++)
                #pragma unroll
                for (int nt = 0; nt < 2; nt++)
                    MMA_TF32(acc[mt][nt], af[mt], bf[nt]);
        }
        if (more) {
            buf ^= 1;
            *(float4*)&As[buf][row][lk8]     = tf32x4(pa0);
            *(float4*)&As[buf][row][lk8 + 4] = tf32x4(pa1);
            *(float4*)&Ws[buf][row][lk8]     = tf32x4(pw0);
            *(float4*)&Ws[buf][row][lk8 + 4] = tf32x4(pw1);
            __syncthreads();
        }
    }

    #pragma unroll
    for (int mt = 0; mt < 2; mt++) {
        int m = wm * 32 + mt * 16 + g;
        bool ok0 = !lengths || (lengths[m] - 1 >= t);
        bool ok1 = !lengths || (lengths[m + 8] - 1 >= t);
        #pragma unroll
        for (int nt = 0; nt < 2; nt++) {
            int n = n0 + wn * 16 + nt * 8 + u * 2;
            float b0 = (bias && n     < N) ? bias[n]     : 0.f;
            float b1 = (bias && n + 1 < N) ? bias[n + 1] : 0.f;
            float v0 = acc[mt][nt][0] + b0, v1 = acc[mt][nt][1] + b1;
            float v2 = acc[mt][nt][2] + b0, v3 = acc[mt][nt][3] + b1;
            if (act == 1) { v0 = fsig(v0); v1 = fsig(v1); v2 = fsig(v2); v3 = fsig(v3); }
            if (ok0) {
                if (n     < N) C[(size_t)m * ldc + n]     = v0;
                if (n + 1 < N) C[(size_t)m * ldc + n + 1] = v1;
            }
            if (ok1) {
                if (n     < N) C[(size_t)(m + 8) * ldc + n]     = v2;
                if (n + 1 < N) C[(size_t)(m + 8) * ldc + n + 1] = v3;
            }
        }
    }
}

// ---------------- TC GRU gate GEMMs: gi split-K x4 (blk 0..95) + gh (96..119)
// A built on the fly: gi -> gate*z | embed ; gh -> g_h. Partials, no bias.
__global__ void __launch_bounds__(256)
k_gates_tc(const float* __restrict__ w_ih, const float* __restrict__ w_hh,
           const float* __restrict__ embed, const int* __restrict__ captions,
           int t) {
    int blk = blockIdx.x;
    bool is_gi = blk < NB3H * GI_SPLITS;
    int s     = is_gi ? (blk / NB3H) : 0;
    int n0    = (is_gi ? (blk % NB3H) : (blk - NB3H * GI_SPLITS)) * 64;
    int kbase = is_gi ? s * GI_KCHUNK : 0;
    int Klen  = is_gi ? GI_KCHUNK : H_;
    int Kfull = is_gi ? (E_ + EMB_) : H_;
    const float* W = is_gi ? w_ih : w_hh;
    float* C       = is_gi ? g_gip[s] : g_gh;

    __shared__ __align__(16) float As[2][64][36];
    __shared__ __align__(16) float Ws[2][64][36];
    int tid = threadIdx.x;
    int row = tid >> 2;            // 0..63  (batch row for A, weight row for W)
    int lk8 = (tid & 3) * 8;
    int wid = tid >> 5, lane = tid & 31;
    int wm = wid & 1, wn = wid >> 1;
    int g = lane >> 2, u = lane & 3;

    float acc[2][2][4] = {};
    float4 pa0, pa1, pw0, pw1;

    #define FETCH_A4(kg, dst) do {                                            \
        if (is_gi) {                                                          \
            if ((kg) < E_) {                                                  \
                float4 gg = *(const float4*)&g_gate[(size_t)row * E_ + (kg)]; \
                float4 zz = *(const float4*)&g_z[(size_t)row * E_ + (kg)];    \
                dst = make_float4(gg.x*zz.x, gg.y*zz.y, gg.z*zz.z, gg.w*zz.w);\
            } else {                                                          \
                int cap = captions[row * TCAP + t];                           \
                dst = *(const float4*)&embed[(size_t)cap * EMB_ + ((kg) - E_)];\
            }                                                                 \
        } else {                                                              \
            dst = *(const float4*)&g_h[(size_t)row * H_ + (kg)];              \
        }                                                                     \
    } while (0)

    FETCH_A4(kbase + lk8,     pa0);
    FETCH_A4(kbase + lk8 + 4, pa1);
    pw0 = *(const float4*)&W[(size_t)(n0 + row) * Kfull + kbase + lk8];
    pw1 = *(const float4*)&W[(size_t)(n0 + row) * Kfull + kbase + lk8 + 4];
    *(float4*)&As[0][row][lk8]     = tf32x4(pa0);
    *(float4*)&As[0][row][lk8 + 4] = tf32x4(pa1);
    *(float4*)&Ws[0][row][lk8]     = tf32x4(pw0);
    *(float4*)&Ws[0][row][lk8 + 4] = tf32x4(pw1);
    __syncthreads();

    int buf = 0;
    for (int k0 = 0; k0 < Klen; k0 += 32) {
        bool more = (k0 + 32) < Klen;
        if (more) {
            int kg = kbase + k0 + 32 + lk8;
            FETCH_A4(kg,     pa0);
            FETCH_A4(kg + 4, pa1);
            pw0 = *(const float4*)&W[(size_t)(n0 + row) * Kfull + kg];
            pw1 = *(const float4*)&W[(size_t)(n0 + row) * Kfull + kg + 4];
        }
        #pragma unroll
        for (int ks = 0; ks < 32; ks += 8) {
            unsigned int af[2][4], bf[2][2];
            #pragma unroll
            for (int mt = 0; mt < 2; mt++) {
                int mb = wm * 32 + mt * 16;
                af[mt][0] = __float_as_uint(As[buf][mb + g    ][ks + u    ]);
                af[mt][1] = __float_as_uint(As[buf][mb + g + 8][ks + u    ]);
                af[mt][2] = __float_as_uint(As[buf][mb + g    ][ks + u + 4]);
                af[mt][3] = __float_as_uint(As[buf][mb + g + 8][ks + u + 4]);
            }
            #pragma unroll
            for (int nt = 0; nt < 2; nt++) {
                int nb = wn * 16 + nt * 8;
                bf[nt][0] = __float_as_uint(Ws[buf][nb + g][ks + u    ]);
                bf[nt][1] = __float_as_uint(Ws[buf][nb + g][ks + u + 4]);
            }
            #pragma unroll
            for (int mt = 0; mt < 2; mt++)
                #pragma unroll
                for (int nt = 0; nt < 2; nt++)
                    MMA_TF32(acc[mt][nt], af[mt], bf[nt]);
        }
        if (more) {
            buf ^= 1;
            *(float4*)&As[buf][row][lk8]     = tf32x4(pa0);
            *(float4*)&As[buf][row][lk8 + 4] = tf32x4(pa1);
            *(float4*)&Ws[buf][row][lk8]     = tf32x4(pw0);
            *(float4*)&Ws[buf][row][lk8 + 4] = tf32x4(pw1);
            __syncthreads();
        }
    }
    #undef FETCH_A4

    #pragma unroll
    for (int mt = 0; mt < 2; mt++) {
        int m = wm * 32 + mt * 16 + g;
        #pragma unroll
        for (int nt = 0; nt < 2; nt++) {
            int n = n0 + wn * 16 + nt * 8 + u * 2;
            C[(size_t)m * (3*H_) + n]           = acc[mt][nt][0];
            C[(size_t)m * (3*H_) + n + 1]       = acc[mt][nt][1];
            C[(size_t)(m + 8) * (3*H_) + n]     = acc[mt][nt][2];
            C[(size_t)(m + 8) * (3*H_) + n + 1] = acc[mt][nt][3];
        }
    }
}

// ---------------- attention: lam[b,p] = V . tanh(xwx16[b,p]+h_wh[b]) + Vb --
__global__ void k_lam(const float* __restrict__ Vw, const float* __restrict__ Vb) {
    int bp = blockIdx.x;
    int b  = bp / P_;
    int tid = threadIdx.x;
    const uint2*  xw2 = (const uint2*)(g_xwx + (size_t)bp * E_);
    const float4* hw4 = (const float4*)(g_hwh + (size_t)b * E_);
    const float4* vw4 = (const float4*)Vw;
    float s = 0.f;
    #pragma unroll
    for (int q = 0; q < 2; q++) {
        int i = tid * 2 + q;
        uint2 u = xw2[i];
        float2 fa = __half22float2(*(__half2*)&u.x);
        float2 fb = __half22float2(*(__half2*)&u.y);
        float4 h = hw4[i];
        float4 v = vw4[i];
        s += ftanh(fa.x + h.x) * v.x + ftanh(fa.y + h.y) * v.y
           + ftanh(fb.x + h.z) * v.z + ftanh(fb.y + h.w) * v.w;
    }
    __shared__ float red[8];
    int lane = tid & 31, w = tid >> 5;
    #pragma unroll
    for (int o = 16; o > 0; o >>= 1) s += __shfl_xor_sync(0xffffffffu, s, o);
    if (lane == 0) red[w] = s;
    __syncthreads();
    if (tid == 0) {
        float tot = 0.f;
        #pragma unroll
        for (int i = 0; i < 8; i++) tot += red[i];
        g_lam[bp] = tot + Vb[0];
    }
}

// ---------------- fused softmax + z ----------------------------------------
__global__ void k_z(float* __restrict__ out_alphas, const int* __restrict__ lengths, int t) {
    int b  = blockIdx.x >> 1;
    int tid = threadIdx.x;
    int lane = tid & 31, w = tid >> 5;
    __shared__ float red[8];
    __shared__ float bmax, bsum;
    __shared__ float al[P_];

    float v = (tid < P_) ? g_lam[b * P_ + tid] : -3.4e38f;
    float m = v;
    #pragma unroll
    for (int o = 16; o > 0; o >>= 1) m = fmaxf(m, __shfl_xor_sync(0xffffffffu, m, o));
    if (lane == 0) red[w] = m;
    __syncthreads();
    if (tid == 0) {
        float mm = red[0];
        #pragma unroll
        for (int i = 1; i < 8; i++) mm = fmaxf(mm, red[i]);
        bmax = mm;
    }
    __syncthreads();
    float ex = (tid < P_) ? __expf(v - bmax) : 0.f;
    float s = ex;
    #pragma unroll
    for (int o = 16; o > 0; o >>= 1) s += __shfl_xor_sync(0xffffffffu, s, o);
    if (lane == 0) red[w] = s;
    __syncthreads();
    if (tid == 0) {
        float ss = 0.f;
        #pragma unroll
        for (int i = 0; i < 8; i++) ss += red[i];
        bsum = ss;
    }
    __syncthreads();
    if (tid < P_) {
        float a = ex / bsum;
        al[tid] = a;
        if (((blockIdx.x & 1) == 0) && (lengths[b] - 1 >= t))
            out_alphas[(size_t)b * TCAP * P_ + (size_t)t * P_ + tid] = a;
    }
    __syncthreads();

    int e4 = ((blockIdx.x & 1) << 8) + tid;
    const uint2* fp = (const uint2*)(g_feat16 + (size_t)b * P_ * E_) + e4;
    float4 acc = make_float4(0.f, 0.f, 0.f, 0.f);
    #pragma unroll 4
    for (int p = 0; p < P_; p++) {
        float a = al[p];
        uint2 u = fp[(size_t)p * (E_/4)];
        float2 fa = __half22float2(*(__half2*)&u.x);
        float2 fb = __half22float2(*(__half2*)&u.y);
        acc.x += a * fa.x; acc.y += a * fa.y; acc.z += a * fb.x; acc.w += a * fb.y;
    }
    ((float4*)(g_z + (size_t)b * E_))[e4] = acc;
}

// ---------------- GRU cell: sum split parts + biases + masked h update -----
__global__ void k_gru(const float* __restrict__ b_ih, const float* __restrict__ b_hh,
                      const int* __restrict__ lengths, int t) {
    int i = blockIdx.x * 256 + threadIdx.x;   // B*H
    int b = i / H_, j = i % H_;
    size_t base = (size_t)b * 3 * H_;
    float gi_r = b_ih[j],        gi_z = b_ih[H_ + j],        gi_n = b_ih[2*H_ + j];
    #pragma unroll
    for (int s = 0; s < GI_SPLITS; s++) {
        gi_r += g_gip[s][base + j];
        gi_z += g_gip[s][base + H_ + j];
        gi_n += g_gip[s][base + 2*H_ + j];
    }
    float gh_r = g_gh[base + j]        + b_hh[j];
    float gh_z = g_gh[base + H_ + j]   + b_hh[H_ + j];
    float gh_n = g_gh[base + 2*H_ + j] + b_hh[2*H_ + j];
    float r  = fsig(gi_r + gh_r);
    float zg = fsig(gi_z + gh_z);
    float n  = ftanh(gi_n + r * gh_n);
    float h  = g_h[i];
    float hn = (1.f - zg) * n + zg * h;
    if (lengths[b] - 1 >= t) g_h[i] = hn;
}

// ---------------- host driver ----------------------------------------------
extern "C" void kernel_launch(void* const* d_in, const int* in_sizes, int n_in,
                              void* d_out, int out_size) {
    const float* features  = (const float*)d_in[0];
    const int*   captions  = (const int*)  d_in[1];
    const int*   lengths   = (const int*)  d_in[2];
    const float* Wx_w      = (const float*)d_in[3];
    const float* Wx_b      = (const float*)d_in[4];
    const float* Wh_w      = (const float*)d_in[5];
    const float* Wh_b      = (const float*)d_in[6];
    const float* V_w       = (const float*)d_in[7];
    const float* V_b       = (const float*)d_in[8];
    const float* init_h_w  = (const float*)d_in[9];
    const float* init_h_b  = (const float*)d_in[10];
    const float* f_beta_w  = (const float*)d_in[11];
    const float* f_beta_b  = (const float*)d_in[12];
    const float* embed_w   = (const float*)d_in[13];
    const float* gru_w_ih  = (const float*)d_in[14];
    const float* gru_b_ih  = (const float*)d_in[15];
    const float* gru_w_hh  = (const float*)d_in[16];
    const float* gru_b_hh  = (const float*)d_in[17];
    const float* fc1_w     = (const float*)d_in[18];
    const float* fc1_b     = (const float*)d_in[19];
    float* out = (float*)d_out;

    __half *p_xwx;
    float *p_fmean, *p_h, *p_hwh, *p_gate;
    cudaGetSymbolAddress((void**)&p_xwx,   g_xwx);
    cudaGetSymbolAddress((void**)&p_fmean, g_fmean);
    cudaGetSymbolAddress((void**)&p_h,     g_h);
    cudaGetSymbolAddress((void**)&p_hwh,   g_hwh);
    cudaGetSymbolAddress((void**)&p_gate,  g_gate);

    k_zero<<<2048, 256>>>(out, lengths);
    k_feat16<<<(MP_*E_/4)/256, 256>>>(features);
    k_fmean<<<(B_*E_/4)/256, 256>>>(features);
    // h0 = fmean @ init_h^T + b   (N=512, K=2048)
    k_tc64<<<H_/64, 256>>>(p_fmean, init_h_w, init_h_b, p_h,
                           H_, E_, H_, 0, nullptr, 0);
    // x_wx (tensor cores, fp16 out)
    k_gemm_tc<<<dim3(E_/128, MP_/128), 256>>>(features, Wx_w, Wx_b, p_xwx, E_, E_);

    for (int t = 0; t < TMAX; t++) {
        // h_wh = h @ Wh^T + b     (N=2048, K=512)
        k_tc64<<<E_/64, 256>>>(p_h, Wh_w, Wh_b, p_hwh, E_, H_, E_, 0, nullptr, 0);
        // gate = sigmoid(h @ f_beta^T + b)
        k_tc64<<<E_/64, 256>>>(p_h, f_beta_w, f_beta_b, p_gate, E_, H_, E_, 1, nullptr, 0);
        // attention scores + softmax/z
        k_lam<<<MP_, 256>>>(V_w, V_b);
        k_z<<<B_*2, 256>>>(out + PRED_SZ, lengths, t);
        // GRU gate GEMMs (TC, gi split-K x4 + gh)
        k_gates_tc<<<NB3H*GI_SPLITS + NB3H, 256>>>(gru_w_ih, gru_w_hh, embed_w, captions, t);
        k_gru<<<(B_*H_)/256, 256>>>(gru_b_ih, gru_b_hh, lengths, t);
        // pred = h_new @ fc1^T + b  (N=10000, K=512, masked rows)
        k_tc64<<<(V_ + 63)/64, 256>>>(p_h, fc1_w, fc1_b, out + (size_t)t * V_,
                                      V_, H_, TCAP * V_, 0, lengths, t);
    }
}

// round 12
// speedup vs baseline: 3.1116x; 1.2398x over previous
#include <cuda_runtime.h>
#include <cuda_fp16.h>

#define B_    64
#define P_    196
#define E_    2048
#define H_    512
#define EMB_  512
#define V_    10000
#define TCAP  50
#define TMAX  49
#define MP_   (B_*P_)            /* 12544 */

#define PRED_SZ  ((size_t)B_*TCAP*V_)   /* 32,000,000 */
#define ALPHA_SZ ((size_t)B_*TCAP*P_)   /* 627,200 */

#define NB3H  ((3*H_)/64)        /* 24 N-blocks (64 cols) for GRU gate GEMMs */
#define GI_SPLITS 4
#define GI_KCHUNK ((E_+EMB_)/GI_SPLITS)   /* 640 */
#define PREDB ((V_ + 63)/64)     /* 157 pred N-blocks */

// ---------------- scratch (device globals; no allocation allowed) ----------
__device__ __half g_xwx[(size_t)MP_*E_];    // ~51.5 MB (fp16)
__device__ __half g_feat16[(size_t)MP_*E_]; // ~51.5 MB (fp16 copy of features)
__device__ float g_fmean[B_*E_];
__device__ float g_h[B_*H_];
__device__ float g_hwh[B_*E_];
__device__ float g_lam[B_*P_];
__device__ float g_z[B_*E_];
__device__ float g_gate[B_*E_];
__device__ float g_gip[GI_SPLITS][B_*3*H_];  // split-K partials for gi (no bias)
__device__ float g_gh[B_*3*H_];              // gh partial (no bias)

// ---------------- fast math ------------------------------------------------
__device__ __forceinline__ float ftanh(float x) {
    float y;
    asm("tanh.approx.f32 %0, %1;" : "=f"(y) : "f"(x));
    return y;
}
__device__ __forceinline__ float fsig(float x) {
    return 1.f / (1.f + __expf(-x));
}
__device__ __forceinline__ unsigned int f2tf32(float x) {
    unsigned int u;
    asm("cvt.rna.tf32.f32 %0, %1;" : "=r"(u) : "f"(x));
    return u;
}
__device__ __forceinline__ float4 tf32x4(float4 v) {
    v.x = __uint_as_float(f2tf32(v.x));
    v.y = __uint_as_float(f2tf32(v.y));
    v.z = __uint_as_float(f2tf32(v.z));
    v.w = __uint_as_float(f2tf32(v.w));
    return v;
}
#define MMA_TF32(acc, af, bf)                                                  \
    asm volatile(                                                              \
        "mma.sync.aligned.m16n8k8.row.col.f32.tf32.tf32.f32 "                  \
        "{%0,%1,%2,%3}, {%4,%5,%6,%7}, {%8,%9}, {%0,%1,%2,%3};"                \
        : "+f"((acc)[0]), "+f"((acc)[1]), "+f"((acc)[2]), "+f"((acc)[3])       \
        : "r"((af)[0]), "r"((af)[1]), "r"((af)[2]), "r"((af)[3]),              \
          "r"((bf)[0]), "r"((bf)[1]))

// ---------------- zero output + write dec ----------------------------------
__global__ void k_zero(float* out, const int* lengths) {
    size_t n = PRED_SZ + ALPHA_SZ;
    size_t i = (size_t)blockIdx.x * blockDim.x + threadIdx.x;
    size_t stride = (size_t)gridDim.x * blockDim.x;
    for (size_t j = i; j < n; j += stride) out[j] = 0.f;
    if (i < B_) out[PRED_SZ + ALPHA_SZ + i] = (float)(lengths[i] - 1);
}

// ---------------- features -> fp16 copy ------------------------------------
__global__ void k_feat16(const float* __restrict__ feat) {
    size_t i = (size_t)blockIdx.x * 256 + threadIdx.x;   // over MP_*E_/4
    float4 v = ((const float4*)feat)[i];
    __half2 a = __floats2half2_rn(v.x, v.y);
    __half2 b = __floats2half2_rn(v.z, v.w);
    uint2 u;
    u.x = *(unsigned int*)&a;
    u.y = *(unsigned int*)&b;
    ((uint2*)g_feat16)[i] = u;
}

// ---------------- feature mean over P (float4) -----------------------------
__global__ void k_fmean(const float* __restrict__ feat) {
    int i = blockIdx.x * 256 + threadIdx.x;   // over B*E/4
    int b = i / (E_/4), e4 = i % (E_/4);
    const float4* fp = (const float4*)(feat + (size_t)b * P_ * E_) + e4;
    float4 s = make_float4(0.f, 0.f, 0.f, 0.f);
    #pragma unroll 4
    for (int p = 0; p < P_; p++) {
        float4 v = fp[(size_t)p * (E_/4)];
        s.x += v.x; s.y += v.y; s.z += v.z; s.w += v.w;
    }
    const float inv = 1.f / P_;
    s.x *= inv; s.y *= inv; s.z *= inv; s.w *= inv;
    ((float4*)g_fmean)[i] = s;
}

// ---------------- tf32 tensor-core GEMM: xwx(half) = A @ W^T + bias --------
// 128x128 tile, BK=16, 8 warps (2M x 4N), warp tile 64x32. (proven)
__global__ void __launch_bounds__(256, 2)
k_gemm_tc(const float* __restrict__ A, const float* __restrict__ W,
          const float* __restrict__ bias, __half* __restrict__ C,
          int N, int K) {
    __shared__ __align__(16) float As[2][128][20];
    __shared__ __align__(16) float Ws[2][128][20];
    int tid = threadIdx.x;
    int m0 = blockIdx.y * 128, n0 = blockIdx.x * 128;
    int lr = tid >> 2;
    int lk = (tid & 3) * 4;
    int wid  = tid >> 5;
    int lane = tid & 31;
    int wm = wid & 1;
    int wn = wid >> 1;
    int g = lane >> 2, u = lane & 3;

    float acc[4][4][4] = {};

    #pragma unroll
    for (int r = 0; r < 2; r++) {
        int row = lr + r * 64;
        float4 v = tf32x4(*(const float4*)&A[(size_t)(m0 + row) * K + lk]);
        As[0][row][lk+0] = v.x; As[0][row][lk+1] = v.y; As[0][row][lk+2] = v.z; As[0][row][lk+3] = v.w;
        float4 w = tf32x4(*(const float4*)&W[(size_t)(n0 + row) * K + lk]);
        Ws[0][row][lk+0] = w.x; Ws[0][row][lk+1] = w.y; Ws[0][row][lk+2] = w.z; Ws[0][row][lk+3] = w.w;
    }
    __syncthreads();

    int buf = 0;
    for (int k0 = 0; k0 < K; k0 += 16) {
        bool more = (k0 + 16) < K;
        float4 pv[2], pw[2];
        if (more) {
            #pragma unroll
            for (int r = 0; r < 2; r++) {
                int row = lr + r * 64;
                pv[r] = *(const float4*)&A[(size_t)(m0 + row) * K + k0 + 16 + lk];
                pw[r] = *(const float4*)&W[(size_t)(n0 + row) * K + k0 + 16 + lk];
            }
        }
        #pragma unroll
        for (int ks = 0; ks < 16; ks += 8) {
            unsigned int af[4][4], bf[4][2];
            #pragma unroll
            for (int mt = 0; mt < 4; mt++) {
                int mb = wm * 64 + mt * 16;
                af[mt][0] = __float_as_uint(As[buf][mb + g    ][ks + u    ]);
                af[mt][1] = __float_as_uint(As[buf][mb + g + 8][ks + u    ]);
                af[mt][2] = __float_as_uint(As[buf][mb + g    ][ks + u + 4]);
                af[mt][3] = __float_as_uint(As[buf][mb + g + 8][ks + u + 4]);
            }
            #pragma unroll
            for (int nt = 0; nt < 4; nt++) {
                int nb = wn * 32 + nt * 8;
                bf[nt][0] = __float_as_uint(Ws[buf][nb + g][ks + u    ]);
                bf[nt][1] = __float_as_uint(Ws[buf][nb + g][ks + u + 4]);
            }
            #pragma unroll
            for (int mt = 0; mt < 4; mt++)
                #pragma unroll
                for (int nt = 0; nt < 4; nt++)
                    MMA_TF32(acc[mt][nt], af[mt], bf[nt]);
        }
        if (more) {
            int nb = buf ^ 1;
            #pragma unroll
            for (int r = 0; r < 2; r++) {
                int row = lr + r * 64;
                float4 v = tf32x4(pv[r]);
                As[nb][row][lk+0] = v.x; As[nb][row][lk+1] = v.y; As[nb][row][lk+2] = v.z; As[nb][row][lk+3] = v.w;
                float4 w = tf32x4(pw[r]);
                Ws[nb][row][lk+0] = w.x; Ws[nb][row][lk+1] = w.y; Ws[nb][row][lk+2] = w.z; Ws[nb][row][lk+3] = w.w;
            }
            __syncthreads();
            buf = nb;
        }
    }

    #pragma unroll
    for (int mt = 0; mt < 4; mt++) {
        #pragma unroll
        for (int nt = 0; nt < 4; nt++) {
            int m = m0 + wm * 64 + mt * 16 + g;
            int n = n0 + wn * 32 + nt * 8 + u * 2;
            float b0 = bias[n], b1 = bias[n + 1];
            __half2 h0 = __floats2half2_rn(acc[mt][nt][0] + b0, acc[mt][nt][1] + b1);
            *(__half2*)&C[(size_t)m * N + n] = h0;
            __half2 h1 = __floats2half2_rn(acc[mt][nt][2] + b0, acc[mt][nt][3] + b1);
            *(__half2*)&C[(size_t)(m + 8) * N + n] = h1;
        }
    }
}

// ---------------- tf32 TC skinny GEMM core (shared mem passed in) ----------
// M=64, one 64-col N tile at n0, BK=32, 8 warps as 2(M)x4(N), warp tile 32x16.
__device__ __forceinline__ void tc64_core(
    float (&As)[2][64][36], float (&Ws)[2][64][36],
    const float* __restrict__ A, const float* __restrict__ W,
    const float* __restrict__ bias, float* __restrict__ C,
    int N, int K, int ldc, int act,
    const int* __restrict__ lengths, int t, int n0) {
    int tid = threadIdx.x;
    int row = tid >> 2;            // 0..63
    int lk8 = (tid & 3) * 8;       // 0,8,16,24
    int wid = tid >> 5, lane = tid & 31;
    int wm = wid & 1, wn = wid >> 1;
    int g = lane >> 2, u = lane & 3;
    int wrow = n0 + row; if (wrow >= N) wrow = N - 1;   // clamp (tail tile)

    float acc[2][2][4] = {};
    float4 pa0, pa1, pw0, pw1;

    pa0 = *(const float4*)&A[(size_t)row * K + lk8];
    pa1 = *(const float4*)&A[(size_t)row * K + lk8 + 4];
    pw0 = *(const float4*)&W[(size_t)wrow * K + lk8];
    pw1 = *(const float4*)&W[(size_t)wrow * K + lk8 + 4];
    *(float4*)&As[0][row][lk8]     = tf32x4(pa0);
    *(float4*)&As[0][row][lk8 + 4] = tf32x4(pa1);
    *(float4*)&Ws[0][row][lk8]     = tf32x4(pw0);
    *(float4*)&Ws[0][row][lk8 + 4] = tf32x4(pw1);
    __syncthreads();

    int buf = 0;
    for (int k0 = 0; k0 < K; k0 += 32) {
        bool more = (k0 + 32) < K;
        if (more) {
            pa0 = *(const float4*)&A[(size_t)row * K + k0 + 32 + lk8];
            pa1 = *(const float4*)&A[(size_t)row * K + k0 + 32 + lk8 + 4];
            pw0 = *(const float4*)&W[(size_t)wrow * K + k0 + 32 + lk8];
            pw1 = *(const float4*)&W[(size_t)wrow * K + k0 + 32 + lk8 + 4];
        }
        #pragma unroll
        for (int ks = 0; ks < 32; ks += 8) {
            unsigned int af[2][4], bf[2][2];
            #pragma unroll
            for (int mt = 0; mt < 2; mt++) {
                int mb = wm * 32 + mt * 16;
                af[mt][0] = __float_as_uint(As[buf][mb + g    ][ks + u    ]);
                af[mt][1] = __float_as_uint(As[buf][mb + g + 8][ks + u    ]);
                af[mt][2] = __float_as_uint(As[buf][mb + g    ][ks + u + 4]);
                af[mt][3] = __float_as_uint(As[buf][mb + g + 8][ks + u + 4]);
            }
            #pragma unroll
            for (int nt = 0; nt < 2; nt++) {
                int nb = wn * 16 + nt * 8;
                bf[nt][0] = __float_as_uint(Ws[buf][nb + g][ks + u    ]);
                bf[nt][1] = __float_as_uint(Ws[buf][nb + g][ks + u + 4]);
            }
            #pragma unroll
            for (int mt = 0; mt < 2; mt++)
                #pragma unroll
                for (int nt = 0; nt < 2; nt++)
                    MMA_TF32(acc[mt][nt], af[mt], bf[nt]);
        }
        if (more) {
            buf ^= 1;
            *(float4*)&As[buf][row][lk8]     = tf32x4(pa0);
            *(float4*)&As[buf][row][lk8 + 4] = tf32x4(pa1);
            *(float4*)&Ws[buf][row][lk8]     = tf32x4(pw0);
            *(float4*)&Ws[buf][row][lk8 + 4] = tf32x4(pw1);
            __syncthreads();
        }
    }

    #pragma unroll
    for (int mt = 0; mt < 2; mt++) {
        int m = wm * 32 + mt * 16 + g;
        bool ok0 = !lengths || (lengths[m] - 1 >= t);
        bool ok1 = !lengths || (lengths[m + 8] - 1 >= t);
        #pragma unroll
        for (int nt = 0; nt < 2; nt++) {
            int n = n0 + wn * 16 + nt * 8 + u * 2;
            float b0 = (n     < N) ? bias[n]     : 0.f;
            float b1 = (n + 1 < N) ? bias[n + 1] : 0.f;
            float v0 = acc[mt][nt][0] + b0, v1 = acc[mt][nt][1] + b1;
            float v2 = acc[mt][nt][2] + b0, v3 = acc[mt][nt][3] + b1;
            if (act == 1) { v0 = fsig(v0); v1 = fsig(v1); v2 = fsig(v2); v3 = fsig(v3); }
            if (ok0) {
                if (n     < N) C[(size_t)m * ldc + n]     = v0;
                if (n + 1 < N) C[(size_t)m * ldc + n + 1] = v1;
            }
            if (ok1) {
                if (n     < N) C[(size_t)(m + 8) * ldc + n]     = v2;
                if (n + 1 < N) C[(size_t)(m + 8) * ldc + n + 1] = v3;
            }
        }
    }
}

// ---------------- standalone skinny GEMM (h0, pre-loop h_wh/gate) ----------
__global__ void __launch_bounds__(256)
k_tc64(const float* __restrict__ A, const float* __restrict__ W,
       const float* __restrict__ bias, float* __restrict__ C,
       int N, int K, int ldc, int act,
       const int* __restrict__ lengths, int t) {
    __shared__ __align__(16) float As[2][64][36];
    __shared__ __align__(16) float Ws[2][64][36];
    tc64_core(As, Ws, A, W, bias, C, N, K, ldc, act, lengths, t, blockIdx.x * 64);
}

// ---------------- fused post-GRU GEMMs: pred(t) + h_wh(t+1) + gate(t+1) ----
// blocks 0..156: pred (masked)   157..188: h_wh    189..220: gate(sigmoid)
__global__ void __launch_bounds__(256)
k_step_fused(const float* __restrict__ fc1_w, const float* __restrict__ fc1_b,
             float* __restrict__ out_pred,
             const float* __restrict__ Wh_w, const float* __restrict__ Wh_b,
             const float* __restrict__ fb_w, const float* __restrict__ fb_b,
             const int* __restrict__ lengths, int t) {
    __shared__ __align__(16) float As[2][64][36];
    __shared__ __align__(16) float Ws[2][64][36];
    int blk = blockIdx.x;
    if (blk < PREDB) {
        tc64_core(As, Ws, g_h, fc1_w, fc1_b, out_pred,
                  V_, H_, TCAP * V_, 0, lengths, t, blk * 64);
    } else if (blk < PREDB + E_/64) {
        tc64_core(As, Ws, g_h, Wh_w, Wh_b, g_hwh,
                  E_, H_, E_, 0, nullptr, 0, (blk - PREDB) * 64);
    } else {
        tc64_core(As, Ws, g_h, fb_w, fb_b, g_gate,
                  E_, H_, E_, 1, nullptr, 0, (blk - PREDB - E_/64) * 64);
    }
}

// ---------------- TC GRU gate GEMMs: gi split-K x4 (blk 0..95) + gh (96..119)
__global__ void __launch_bounds__(256)
k_gates_tc(const float* __restrict__ w_ih, const float* __restrict__ w_hh,
           const float* __restrict__ embed, const int* __restrict__ captions,
           int t) {
    int blk = blockIdx.x;
    bool is_gi = blk < NB3H * GI_SPLITS;
    int s     = is_gi ? (blk / NB3H) : 0;
    int n0    = (is_gi ? (blk % NB3H) : (blk - NB3H * GI_SPLITS)) * 64;
    int kbase = is_gi ? s * GI_KCHUNK : 0;
    int Klen  = is_gi ? GI_KCHUNK : H_;
    int Kfull = is_gi ? (E_ + EMB_) : H_;
    const float* W = is_gi ? w_ih : w_hh;
    float* C       = is_gi ? g_gip[s] : g_gh;

    __shared__ __align__(16) float As[2][64][36];
    __shared__ __align__(16) float Ws[2][64][36];
    int tid = threadIdx.x;
    int row = tid >> 2;
    int lk8 = (tid & 3) * 8;
    int wid = tid >> 5, lane = tid & 31;
    int wm = wid & 1, wn = wid >> 1;
    int g = lane >> 2, u = lane & 3;

    float acc[2][2][4] = {};
    float4 pa0, pa1, pw0, pw1;

    #define FETCH_A4(kg, dst) do {                                            \
        if (is_gi) {                                                          \
            if ((kg) < E_) {                                                  \
                float4 gg = *(const float4*)&g_gate[(size_t)row * E_ + (kg)]; \
                float4 zz = *(const float4*)&g_z[(size_t)row * E_ + (kg)];    \
                dst = make_float4(gg.x*zz.x, gg.y*zz.y, gg.z*zz.z, gg.w*zz.w);\
            } else {                                                          \
                int cap = captions[row * TCAP + t];                           \
                dst = *(const float4*)&embed[(size_t)cap * EMB_ + ((kg) - E_)];\
            }                                                                 \
        } else {                                                              \
            dst = *(const float4*)&g_h[(size_t)row * H_ + (kg)];              \
        }                                                                     \
    } while (0)

    FETCH_A4(kbase + lk8,     pa0);
    FETCH_A4(kbase + lk8 + 4, pa1);
    pw0 = *(const float4*)&W[(size_t)(n0 + row) * Kfull + kbase + lk8];
    pw1 = *(const float4*)&W[(size_t)(n0 + row) * Kfull + kbase + lk8 + 4];
    *(float4*)&As[0][row][lk8]     = tf32x4(pa0);
    *(float4*)&As[0][row][lk8 + 4] = tf32x4(pa1);
    *(float4*)&Ws[0][row][lk8]     = tf32x4(pw0);
    *(float4*)&Ws[0][row][lk8 + 4] = tf32x4(pw1);
    __syncthreads();

    int buf = 0;
    for (int k0 = 0; k0 < Klen; k0 += 32) {
        bool more = (k0 + 32) < Klen;
        if (more) {
            int kg = kbase + k0 + 32 + lk8;
            FETCH_A4(kg,     pa0);
            FETCH_A4(kg + 4, pa1);
            pw0 = *(const float4*)&W[(size_t)(n0 + row) * Kfull + kg];
            pw1 = *(const float4*)&W[(size_t)(n0 + row) * Kfull + kg + 4];
        }
        #pragma unroll
        for (int ks = 0; ks < 32; ks += 8) {
            unsigned int af[2][4], bf[2][2];
            #pragma unroll
            for (int mt = 0; mt < 2; mt++) {
                int mb = wm * 32 + mt * 16;
                af[mt][0] = __float_as_uint(As[buf][mb + g    ][ks + u    ]);
                af[mt][1] = __float_as_uint(As[buf][mb + g + 8][ks + u    ]);
                af[mt][2] = __float_as_uint(As[buf][mb + g    ][ks + u + 4]);
                af[mt][3] = __float_as_uint(As[buf][mb + g + 8][ks + u + 4]);
            }
            #pragma unroll
            for (int nt = 0; nt < 2; nt++) {
                int nb = wn * 16 + nt * 8;
                bf[nt][0] = __float_as_uint(Ws[buf][nb + g][ks + u    ]);
                bf[nt][1] = __float_as_uint(Ws[buf][nb + g][ks + u + 4]);
            }
            #pragma unroll
            for (int mt = 0; mt < 2; mt++)
                #pragma unroll
                for (int nt = 0; nt < 2; nt++)
                    MMA_TF32(acc[mt][nt], af[mt], bf[nt]);
        }
        if (more) {
            buf ^= 1;
            *(float4*)&As[buf][row][lk8]     = tf32x4(pa0);
            *(float4*)&As[buf][row][lk8 + 4] = tf32x4(pa1);
            *(float4*)&Ws[buf][row][lk8]     = tf32x4(pw0);
            *(float4*)&Ws[buf][row][lk8 + 4] = tf32x4(pw1);
            __syncthreads();
        }
    }
    #undef FETCH_A4

    #pragma unroll
    for (int mt = 0; mt < 2; mt++) {
        int m = wm * 32 + mt * 16 + g;
        #pragma unroll
        for (int nt = 0; nt < 2; nt++) {
            int n = n0 + wn * 16 + nt * 8 + u * 2;
            C[(size_t)m * (3*H_) + n]           = acc[mt][nt][0];
            C[(size_t)m * (3*H_) + n + 1]       = acc[mt][nt][1];
            C[(size_t)(m + 8) * (3*H_) + n]     = acc[mt][nt][2];
            C[(size_t)(m + 8) * (3*H_) + n + 1] = acc[mt][nt][3];
        }
    }
}

// ---------------- attention: lam[b,p] = V . tanh(xwx16[b,p]+h_wh[b]) + Vb --
__global__ void k_lam(const float* __restrict__ Vw, const float* __restrict__ Vb) {
    int bp = blockIdx.x;
    int b  = bp / P_;
    int tid = threadIdx.x;
    const uint2*  xw2 = (const uint2*)(g_xwx + (size_t)bp * E_);
    const float4* hw4 = (const float4*)(g_hwh + (size_t)b * E_);
    const float4* vw4 = (const float4*)Vw;
    float s = 0.f;
    #pragma unroll
    for (int q = 0; q < 2; q++) {
        int i = tid * 2 + q;
        uint2 u = xw2[i];
        float2 fa = __half22float2(*(__half2*)&u.x);
        float2 fb = __half22float2(*(__half2*)&u.y);
        float4 h = hw4[i];
        float4 v = vw4[i];
        s += ftanh(fa.x + h.x) * v.x + ftanh(fa.y + h.y) * v.y
           + ftanh(fb.x + h.z) * v.z + ftanh(fb.y + h.w) * v.w;
    }
    __shared__ float red[8];
    int lane = tid & 31, w = tid >> 5;
    #pragma unroll
    for (int o = 16; o > 0; o >>= 1) s += __shfl_xor_sync(0xffffffffu, s, o);
    if (lane == 0) red[w] = s;
    __syncthreads();
    if (tid == 0) {
        float tot = 0.f;
        #pragma unroll
        for (int i = 0; i < 8; i++) tot += red[i];
        g_lam[bp] = tot + Vb[0];
    }
}

// ---------------- fused softmax + z ----------------------------------------
__global__ void k_z(float* __restrict__ out_alphas, const int* __restrict__ lengths, int t) {
    int b  = blockIdx.x >> 1;
    int tid = threadIdx.x;
    int lane = tid & 31, w = tid >> 5;
    __shared__ float red[8];
    __shared__ float bmax, bsum;
    __shared__ float al[P_];

    float v = (tid < P_) ? g_lam[b * P_ + tid] : -3.4e38f;
    float m = v;
    #pragma unroll
    for (int o = 16; o > 0; o >>= 1) m = fmaxf(m, __shfl_xor_sync(0xffffffffu, m, o));
    if (lane == 0) red[w] = m;
    __syncthreads();
    if (tid == 0) {
        float mm = red[0];
        #pragma unroll
        for (int i = 1; i < 8; i++) mm = fmaxf(mm, red[i]);
        bmax = mm;
    }
    __syncthreads();
    float ex = (tid < P_) ? __expf(v - bmax) : 0.f;
    float s = ex;
    #pragma unroll
    for (int o = 16; o > 0; o >>= 1) s += __shfl_xor_sync(0xffffffffu, s, o);
    if (lane == 0) red[w] = s;
    __syncthreads();
    if (tid == 0) {
        float ss = 0.f;
        #pragma unroll
        for (int i = 0; i < 8; i++) ss += red[i];
        bsum = ss;
    }
    __syncthreads();
    if (tid < P_) {
        float a = ex / bsum;
        al[tid] = a;
        if (((blockIdx.x & 1) == 0) && (lengths[b] - 1 >= t))
            out_alphas[(size_t)b * TCAP * P_ + (size_t)t * P_ + tid] = a;
    }
    __syncthreads();

    int e4 = ((blockIdx.x & 1) << 8) + tid;
    const uint2* fp = (const uint2*)(g_feat16 + (size_t)b * P_ * E_) + e4;
    float4 acc = make_float4(0.f, 0.f, 0.f, 0.f);
    #pragma unroll 4
    for (int p = 0; p < P_; p++) {
        float a = al[p];
        uint2 u = fp[(size_t)p * (E_/4)];
        float2 fa = __half22float2(*(__half2*)&u.x);
        float2 fb = __half22float2(*(__half2*)&u.y);
        acc.x += a * fa.x; acc.y += a * fa.y; acc.z += a * fb.x; acc.w += a * fb.y;
    }
    ((float4*)(g_z + (size_t)b * E_))[e4] = acc;
}

// ---------------- GRU cell: sum split parts + biases + masked h update -----
__global__ void k_gru(const float* __restrict__ b_ih, const float* __restrict__ b_hh,
                      const int* __restrict__ lengths, int t) {
    int i = blockIdx.x * 256 + threadIdx.x;   // B*H
    int b = i / H_, j = i % H_;
    size_t base = (size_t)b * 3 * H_;
    float gi_r = b_ih[j],        gi_z = b_ih[H_ + j],        gi_n = b_ih[2*H_ + j];
    #pragma unroll
    for (int s = 0; s < GI_SPLITS; s++) {
        gi_r += g_gip[s][base + j];
        gi_z += g_gip[s][base + H_ + j];
        gi_n += g_gip[s][base + 2*H_ + j];
    }
    float gh_r = g_gh[base + j]        + b_hh[j];
    float gh_z = g_gh[base + H_ + j]   + b_hh[H_ + j];
    float gh_n = g_gh[base + 2*H_ + j] + b_hh[2*H_ + j];
    float r  = fsig(gi_r + gh_r);
    float zg = fsig(gi_z + gh_z);
    float n  = ftanh(gi_n + r * gh_n);
    float h  = g_h[i];
    float hn = (1.f - zg) * n + zg * h;
    if (lengths[b] - 1 >= t) g_h[i] = hn;
}

// ---------------- host driver ----------------------------------------------
extern "C" void kernel_launch(void* const* d_in, const int* in_sizes, int n_in,
                              void* d_out, int out_size) {
    const float* features  = (const float*)d_in[0];
    const int*   captions  = (const int*)  d_in[1];
    const int*   lengths   = (const int*)  d_in[2];
    const float* Wx_w      = (const float*)d_in[3];
    const float* Wx_b      = (const float*)d_in[4];
    const float* Wh_w      = (const float*)d_in[5];
    const float* Wh_b      = (const float*)d_in[6];
    const float* V_w       = (const float*)d_in[7];
    const float* V_b       = (const float*)d_in[8];
    const float* init_h_w  = (const float*)d_in[9];
    const float* init_h_b  = (const float*)d_in[10];
    const float* f_beta_w  = (const float*)d_in[11];
    const float* f_beta_b  = (const float*)d_in[12];
    const float* embed_w   = (const float*)d_in[13];
    const float* gru_w_ih  = (const float*)d_in[14];
    const float* gru_b_ih  = (const float*)d_in[15];
    const float* gru_w_hh  = (const float*)d_in[16];
    const float* gru_b_hh  = (const float*)d_in[17];
    const float* fc1_w     = (const float*)d_in[18];
    const float* fc1_b     = (const float*)d_in[19];
    float* out = (float*)d_out;

    __half *p_xwx;
    float *p_fmean, *p_h, *p_hwh, *p_gate;
    cudaGetSymbolAddress((void**)&p_xwx,   g_xwx);
    cudaGetSymbolAddress((void**)&p_fmean, g_fmean);
    cudaGetSymbolAddress((void**)&p_h,     g_h);
    cudaGetSymbolAddress((void**)&p_hwh,   g_hwh);
    cudaGetSymbolAddress((void**)&p_gate,  g_gate);

    k_zero<<<2048, 256>>>(out, lengths);
    k_feat16<<<(MP_*E_/4)/256, 256>>>(features);
    k_fmean<<<(B_*E_/4)/256, 256>>>(features);
    // h0 = fmean @ init_h^T + b   (N=512, K=2048)
    k_tc64<<<H_/64, 256>>>(p_fmean, init_h_w, init_h_b, p_h,
                           H_, E_, H_, 0, nullptr, 0);
    // x_wx (tensor cores, fp16 out)
    k_gemm_tc<<<dim3(E_/128, MP_/128), 256>>>(features, Wx_w, Wx_b, p_xwx, E_, E_);
    // pre-loop h_wh(0) + gate(0)
    k_tc64<<<E_/64, 256>>>(p_h, Wh_w, Wh_b, p_hwh, E_, H_, E_, 0, nullptr, 0);
    k_tc64<<<E_/64, 256>>>(p_h, f_beta_w, f_beta_b, p_gate, E_, H_, E_, 1, nullptr, 0);

    for (int t = 0; t < TMAX; t++) {
        // attention scores + softmax/z (uses h_wh/gate computed for this t)
        k_lam<<<MP_, 256>>>(V_w, V_b);
        k_z<<<B_*2, 256>>>(out + PRED_SZ, lengths, t);
        // GRU gate GEMMs (TC, gi split-K x4 + gh)
        k_gates_tc<<<NB3H*GI_SPLITS + NB3H, 256>>>(gru_w_ih, gru_w_hh, embed_w, captions, t);
        k_gru<<<(B_*H_)/256, 256>>>(gru_b_ih, gru_b_hh, lengths, t);
        // fused: pred(t) + h_wh(t+1) + gate(t+1)   (221 blocks)
        k_step_fused<<<PREDB + 2*(E_/64), 256>>>(fc1_w, fc1_b, out + (size_t)t * V_,
                                                 Wh_w, Wh_b, f_beta_w, f_beta_b,
                                                 lengths, t);
    }
}